// round 11
// baseline (speedup 1.0000x reference)
#include <cuda_runtime.h>
#include <cuda_fp16.h>
#include <cstdint>

#define N_NODES   50000
#define N_EDGES   800000
#define D_FEAT    128
#define HIDDEN    256
#define N_PAD     50048          // 391 * 128
#define M_TILES   391
#define SCAN_BLKS 49             // 49 * 1024 = 50176 >= N_NODES
#define LB_FLAG   0x40000000u

// ---------------- scratch (static device globals) ---------------------------
__device__ int   g_deg[N_NODES];
__device__ unsigned int g_lb[SCAN_BLKS];   // lookback: aggregate | LB_FLAG
__device__ int   g_rowptr[N_NODES + 1];
__device__ int   g_cursor[N_NODES];
__device__ float g_invdeg[N_NODES];
__device__ int   g_nbr[N_EDGES];
__device__ __half g_A[(size_t)N_PAD * 256];   // [mean|x] fp16; pad rows stay 0
__device__ __half g_B[256 * 256];             // B^T: [n][k], k-major, fp16
__device__ float g_p[N_NODES * 2];   // h @ W2l (atomic-accumulated)
__device__ float g_q[N_NODES * 2];   // h @ W2r

// ---------------- prep: zero deg/p/q/lb + convert W1 + convert x -------------
__global__ void k_prep(const float* __restrict__ W1l, const float* __restrict__ W1r,
                       const float* __restrict__ x) {
    int i = blockIdx.x * blockDim.x + threadIdx.x;
    if (i < N_NODES) g_deg[i] = 0;
    if (i < N_NODES * 2) { g_p[i] = 0.f; g_q[i] = 0.f; }
    if (i < SCAN_BLKS) g_lb[i] = 0u;
    if (i < 256 * 256) {
        int k = i >> 8, n = i & 255;
        float v = (k < 128) ? W1l[k * 256 + n] : W1r[(k - 128) * 256 + n];
        g_B[n * 256 + k] = __float2half_rn(v);
    }
    if (i < N_NODES * 32) {
        int node = i >> 5, lane = i & 31;
        float4 v = *(const float4*)(x + (size_t)node * D_FEAT + lane * 4);
        uint2 pk;
        __half2 p0 = __floats2half2_rn(v.x, v.y);
        __half2 p1 = __floats2half2_rn(v.z, v.w);
        pk.x = *(uint32_t*)&p0;
        pk.y = *(uint32_t*)&p1;
        size_t off = (size_t)node * 256 + 128 + lane * 4;
        *reinterpret_cast<uint2*>(&g_A[off]) = pk;
    }
}

__global__ void k_hist(const int* __restrict__ dst) {
    int e = blockIdx.x * blockDim.x + threadIdx.x;
    if (e < N_EDGES) atomicAdd(&g_deg[dst[e]], 1);
}

// ---- single-pass scan with decoupled lookback (49 blocks, all one wave) ----
__global__ void k_scan() {
    __shared__ int warp_tot[32];
    __shared__ int s_base;
    int tid = threadIdx.x, lane = tid & 31, wid = tid >> 5;
    int bid = blockIdx.x;

    int idx = bid * 1024 + tid;
    int v = (idx < N_NODES) ? g_deg[idx] : 0;
    int xv = v;
#pragma unroll
    for (int o = 1; o < 32; o <<= 1) {
        int t = __shfl_up_sync(0xffffffffu, xv, o);
        if (lane >= o) xv += t;
    }
    if (lane == 31) warp_tot[wid] = xv;
    __syncthreads();
    if (wid == 0) {
        int w = warp_tot[lane];
        int xw = w;
#pragma unroll
        for (int o = 1; o < 32; o <<= 1) {
            int t = __shfl_up_sync(0xffffffffu, xw, o);
            if (lane >= o) xw += t;
        }
        warp_tot[lane] = xw;            // inclusive warp totals
        // publish own aggregate (block total = xw at lane 31), then look back
        if (lane == 31) atomicExch(&g_lb[bid], (unsigned)xw | LB_FLAG);
        unsigned s0 = 0, s1 = 0;
        if (lane < bid) {
            unsigned val;
            do { val = atomicOr(&g_lb[lane], 0u); } while (!(val & LB_FLAG));
            s0 = val & ~LB_FLAG;
        }
        if (lane + 32 < bid) {
            unsigned val;
            do { val = atomicOr(&g_lb[lane + 32], 0u); } while (!(val & LB_FLAG));
            s1 = val & ~LB_FLAG;
        }
        int s = (int)(s0 + s1);
#pragma unroll
        for (int o = 16; o > 0; o >>= 1) s += __shfl_xor_sync(0xffffffffu, s, o);
        if (lane == 0) s_base = s;
    }
    __syncthreads();
    int base = s_base + ((wid > 0) ? warp_tot[wid - 1] : 0);
    int excl = base + xv - v;
    if (idx < N_NODES) {
        g_rowptr[idx] = excl;
        g_cursor[idx] = excl;
        g_invdeg[idx] = 1.0f / (float)(v > 0 ? v : 1);
    }
    if (bid == SCAN_BLKS - 1 && tid == 1023)
        g_rowptr[N_NODES] = s_base + warp_tot[31];
}

__global__ void k_scatter(const int* __restrict__ src, const int* __restrict__ dst) {
    int e = blockIdx.x * blockDim.x + threadIdx.x;
    if (e < N_EDGES) {
        int d = dst[e];
        int pos = atomicAdd(&g_cursor[d], 1);
        g_nbr[pos] = src[e];
    }
}

// agg layer1 (warp/node): mean of fp16 x, 2-edge unrolled (MLP=2)
__global__ void k_agg1c() {
    int warp = (blockIdx.x * blockDim.x + threadIdx.x) >> 5;
    int lane = threadIdx.x & 31;
    if (warp >= N_NODES) return;
    int beg = g_rowptr[warp], end = g_rowptr[warp + 1];
    float4 acc = make_float4(0.f, 0.f, 0.f, 0.f);
    int j = beg;
    for (; j + 1 < end; j += 2) {
        int s0 = g_nbr[j], s1 = g_nbr[j + 1];
        uint2 pa = *reinterpret_cast<const uint2*>(g_A + (size_t)s0 * 256 + 128 + lane * 4);
        uint2 pb = *reinterpret_cast<const uint2*>(g_A + (size_t)s1 * 256 + 128 + lane * 4);
        float2 a0 = __half22float2(*(const __half2*)&pa.x);
        float2 a1 = __half22float2(*(const __half2*)&pa.y);
        float2 b0 = __half22float2(*(const __half2*)&pb.x);
        float2 b1 = __half22float2(*(const __half2*)&pb.y);
        acc.x += a0.x + b0.x; acc.y += a0.y + b0.y;
        acc.z += a1.x + b1.x; acc.w += a1.y + b1.y;
    }
    if (j < end) {
        int s0 = g_nbr[j];
        uint2 pa = *reinterpret_cast<const uint2*>(g_A + (size_t)s0 * 256 + 128 + lane * 4);
        float2 a0 = __half22float2(*(const __half2*)&pa.x);
        float2 a1 = __half22float2(*(const __half2*)&pa.y);
        acc.x += a0.x; acc.y += a0.y; acc.z += a1.x; acc.w += a1.y;
    }
    float id = g_invdeg[warp];
    __half2 p0 = __floats2half2_rn(acc.x * id, acc.y * id);
    __half2 p1 = __floats2half2_rn(acc.z * id, acc.w * id);
    uint2 pk;
    pk.x = *(uint32_t*)&p0;
    pk.y = *(uint32_t*)&p1;
    size_t off = (size_t)warp * 256 + lane * 4;
    *reinterpret_cast<uint2*>(&g_A[off]) = pk;
}

// ---------------- HMMA GEMM1 (fp16, ldmatrix) + fused layer-2 projections ----
__device__ __forceinline__ uint32_t smem_u32(const void* p) {
    uint32_t a;
    asm("{ .reg .u64 t; cvta.to.shared.u64 t, %1; cvt.u32.u64 %0, t; }" : "=r"(a) : "l"(p));
    return a;
}
__device__ __forceinline__ void ldm_x4(uint32_t* r, uint32_t addr) {
    asm volatile("ldmatrix.sync.aligned.m8n8.x4.shared.b16 {%0,%1,%2,%3}, [%4];"
        : "=r"(r[0]), "=r"(r[1]), "=r"(r[2]), "=r"(r[3]) : "r"(addr));
}
__device__ __forceinline__ void mma_f16(float* d, const uint32_t* a,
                                        uint32_t b0, uint32_t b1) {
    asm volatile(
        "mma.sync.aligned.m16n8k16.row.col.f32.f16.f16.f32 "
        "{%0,%1,%2,%3}, {%4,%5,%6,%7}, {%8,%9}, {%0,%1,%2,%3};"
        : "+f"(d[0]), "+f"(d[1]), "+f"(d[2]), "+f"(d[3])
        : "r"(a[0]), "r"(a[1]), "r"(a[2]), "r"(a[3]), "r"(b0), "r"(b1));
}

__global__ void __launch_bounds__(256)
k_gemm1_mma(const float* __restrict__ b1,
            const float* __restrict__ W2l, const float* __restrict__ W2r,
            float* __restrict__ h) {
    __shared__ char smA[18432];        // 128 rows x 144B
    __shared__ char smB[18432];
    __shared__ float bias[128];
    __shared__ float2 w2l[128];
    __shared__ float2 w2r[128];

    int tid  = threadIdx.x, lane = tid & 31, warp = tid >> 5;
    int warpM = warp & 3, warpN = warp >> 2;
    int m0 = blockIdx.x * 128, n0 = blockIdx.y * 128;
    uint32_t sA = smem_u32(smA), sB = smem_u32(smB);

    if (tid < 128) {
        bias[tid] = b1[n0 + tid];
        w2l[tid]  = ((const float2*)W2l)[n0 + tid];
        w2r[tid]  = ((const float2*)W2r)[n0 + tid];
    }

    float acc[2][8][4];
#pragma unroll
    for (int mt = 0; mt < 2; mt++)
#pragma unroll
        for (int nt = 0; nt < 8; nt++)
#pragma unroll
            for (int j = 0; j < 4; j++) acc[mt][nt][j] = 0.f;

#pragma unroll 1
    for (int c = 0; c < 4; c++) {
        __syncthreads();
#pragma unroll
        for (int t = 0; t < 4; t++) {
            int idx = tid + t * 256;
            int r = idx >> 3, q = idx & 7;
            size_t ga = (size_t)(m0 + r) * 256 + c * 64 + q * 8;
            size_t gb = (size_t)(n0 + r) * 256 + c * 64 + q * 8;
            uint32_t so = (uint32_t)(r * 144 + q * 16);
            *(uint4*)(smA + so) = *(const uint4*)(g_A + ga);
            *(uint4*)(smB + so) = *(const uint4*)(g_B + gb);
        }
        __syncthreads();
#pragma unroll
        for (int s = 0; s < 4; s++) {
            uint32_t a[2][4];
#pragma unroll
            for (int mt = 0; mt < 2; mt++) {
                int row = warpM * 32 + mt * 16 + (lane & 15);
                uint32_t off = (uint32_t)(row * 144 + (s * 16 + (lane >> 4) * 8) * 2);
                ldm_x4(a[mt], sA + off);
            }
            uint32_t b[4][4];
#pragma unroll
            for (int pr = 0; pr < 4; pr++) {
                int nrow = warpN * 64 + pr * 16 + ((lane >> 4) ? 8 : 0) + (lane & 7);
                int koff = s * 16 + (((lane >> 3) & 1) * 8);
                uint32_t off = (uint32_t)(nrow * 144 + koff * 2);
                ldm_x4(b[pr], sB + off);
            }
#pragma unroll
            for (int pr = 0; pr < 4; pr++) {
#pragma unroll
                for (int hf = 0; hf < 2; hf++) {
                    int nt = pr * 2 + hf;
                    uint32_t b0 = b[pr][hf * 2], b1v = b[pr][hf * 2 + 1];
#pragma unroll
                    for (int mt = 0; mt < 2; mt++)
                        mma_f16(acc[mt][nt], a[mt], b0, b1v);
                }
            }
        }
    }

    // epilogue: bias + relu + store h; fused projections p = h@W2l, q = h@W2r
#pragma unroll
    for (int mt = 0; mt < 2; mt++) {
        int rowA = m0 + warpM * 32 + mt * 16 + (lane >> 2);
        int rowB = rowA + 8;
        float pla0 = 0.f, pla1 = 0.f, pra0 = 0.f, pra1 = 0.f;
        float plb0 = 0.f, plb1 = 0.f, prb0 = 0.f, prb1 = 0.f;
#pragma unroll
        for (int nt = 0; nt < 8; nt++) {
            int cl = warpN * 64 + nt * 8 + (lane & 3) * 2;
            float bz0 = bias[cl], bz1 = bias[cl + 1];
            float h0 = fmaxf(acc[mt][nt][0] + bz0, 0.f);
            float h1 = fmaxf(acc[mt][nt][1] + bz1, 0.f);
            float h2 = fmaxf(acc[mt][nt][2] + bz0, 0.f);
            float h3 = fmaxf(acc[mt][nt][3] + bz1, 0.f);
            if (rowA < N_NODES)
                *(float2*)(h + (size_t)rowA * 256 + n0 + cl) = make_float2(h0, h1);
            if (rowB < N_NODES)
                *(float2*)(h + (size_t)rowB * 256 + n0 + cl) = make_float2(h2, h3);
            float2 wl0 = w2l[cl], wl1 = w2l[cl + 1];
            float2 wr0 = w2r[cl], wr1 = w2r[cl + 1];
            pla0 += h0 * wl0.x + h1 * wl1.x;  pla1 += h0 * wl0.y + h1 * wl1.y;
            pra0 += h0 * wr0.x + h1 * wr1.x;  pra1 += h0 * wr0.y + h1 * wr1.y;
            plb0 += h2 * wl0.x + h3 * wl1.x;  plb1 += h2 * wl0.y + h3 * wl1.y;
            prb0 += h2 * wr0.x + h3 * wr1.x;  prb1 += h2 * wr0.y + h3 * wr1.y;
        }
#pragma unroll
        for (int o = 1; o <= 2; o <<= 1) {
            pla0 += __shfl_xor_sync(0xffffffffu, pla0, o);
            pla1 += __shfl_xor_sync(0xffffffffu, pla1, o);
            pra0 += __shfl_xor_sync(0xffffffffu, pra0, o);
            pra1 += __shfl_xor_sync(0xffffffffu, pra1, o);
            plb0 += __shfl_xor_sync(0xffffffffu, plb0, o);
            plb1 += __shfl_xor_sync(0xffffffffu, plb1, o);
            prb0 += __shfl_xor_sync(0xffffffffu, prb0, o);
            prb1 += __shfl_xor_sync(0xffffffffu, prb1, o);
        }
        if ((lane & 3) == 0) {
            if (rowA < N_NODES) {
                atomicAdd(&g_p[rowA * 2 + 0], pla0);
                atomicAdd(&g_p[rowA * 2 + 1], pla1);
                atomicAdd(&g_q[rowA * 2 + 0], pra0);
                atomicAdd(&g_q[rowA * 2 + 1], pra1);
            }
            if (rowB < N_NODES) {
                atomicAdd(&g_p[rowB * 2 + 0], plb0);
                atomicAdd(&g_p[rowB * 2 + 1], plb1);
                atomicAdd(&g_q[rowB * 2 + 0], prb0);
                atomicAdd(&g_q[rowB * 2 + 1], prb1);
            }
        }
    }
}

// ---------------- layer-2: aggregate p, add q, sigmoid, store ----------------
__global__ void k_aggout(const float* __restrict__ b2, float* __restrict__ out) {
    int i = blockIdx.x * blockDim.x + threadIdx.x;
    if (i >= N_NODES) return;
    int beg = g_rowptr[i], end = g_rowptr[i + 1];
    float a0 = 0.f, a1 = 0.f;
    const float2* p2 = (const float2*)g_p;
    int j = beg;
    for (; j + 1 < end; j += 2) {
        float2 v0 = p2[g_nbr[j]];
        float2 v1 = p2[g_nbr[j + 1]];
        a0 += v0.x + v1.x; a1 += v0.y + v1.y;
    }
    if (j < end) {
        float2 v = p2[g_nbr[j]];
        a0 += v.x; a1 += v.y;
    }
    float id = g_invdeg[i];
    float v0 = a0 * id + g_q[i * 2 + 0] + b2[0];
    float v1 = a1 * id + g_q[i * 2 + 1] + b2[1];
    out[i * 2 + 0] = 1.0f / (1.0f + __expf(-v0));
    out[i * 2 + 1] = 1.0f / (1.0f + __expf(-v1));
}

// ---------------- launch ------------------------------------------------------
extern "C" void kernel_launch(void* const* d_in, const int* in_sizes, int n_in,
                              void* d_out, int out_size) {
    const float* x   = (const float*)d_in[0];
    const int*   ei  = (const int*)d_in[1];
    const float* W1l = (const float*)d_in[2];
    const float* W1r = (const float*)d_in[3];
    const float* b1  = (const float*)d_in[4];
    const float* W2l = (const float*)d_in[5];
    const float* W2r = (const float*)d_in[6];
    const float* b2  = (const float*)d_in[7];

    float* out = (float*)d_out;
    float* emb = out + (size_t)N_NODES * 2;

    const int* src = ei;
    const int* dst = ei + N_EDGES;

    // prep: zero deg/p/q/lookback + convert W1 + convert x (one kernel)
    k_prep<<<(N_NODES * 32 + 255) / 256, 256>>>(W1l, W1r, x);

    // CSR build (single-pass lookback scan)
    k_hist<<<(N_EDGES + 255) / 256, 256>>>(dst);
    k_scan<<<SCAN_BLKS, 1024>>>();
    k_scatter<<<(N_EDGES + 255) / 256, 256>>>(src, dst);

    // layer 1 aggregation (fp16 reads, MLP=2) + A conversion
    k_agg1c<<<(N_NODES + 7) / 8, 256>>>();

    // layer-1 GEMM (fp16 HMMA + ldmatrix) + fused layer-2 projections
    dim3 g1(M_TILES, 2);
    k_gemm1_mma<<<g1, 256>>>(b1, W2l, W2r, emb);

    // layer-2: aggregate 2-dim projections + output
    k_aggout<<<(N_NODES + 255) / 256, 256>>>(b2, out);
}

// round 12
// speedup vs baseline: 1.0018x; 1.0018x over previous
#include <cuda_runtime.h>
#include <cuda_fp16.h>
#include <cstdint>

#define N_NODES   50000
#define N_EDGES   800000
#define D_FEAT    128
#define HIDDEN    256
#define N_PAD     50048          // 391 * 128
#define M_TILES   391
#define SCAN_BLKS 49             // 49 * 1024 = 50176 >= N_NODES
#define LB_FLAG   0x40000000u

// ---------------- scratch (static device globals) ---------------------------
__device__ int   g_deg[N_NODES];
__device__ unsigned int g_lb[SCAN_BLKS];   // lookback: aggregate | LB_FLAG
__device__ int   g_rowptr[N_NODES + 1];
__device__ float g_invdeg[N_NODES];
__device__ int   g_ord[N_EDGES];     // per-edge ordinal within destination
__device__ int   g_nbr[N_EDGES];
__device__ __half g_A[(size_t)N_PAD * 256];   // [mean|x] fp16; pad rows stay 0
__device__ __half g_B[256 * 256];             // B^T: [n][k], k-major, fp16
__device__ float g_p[N_NODES * 2];   // h @ W2l (atomic-accumulated)
__device__ float g_q[N_NODES * 2];   // h @ W2r

// ---------------- prep: zero deg/p/q/lb + convert W1 + convert x -------------
__global__ void k_prep(const float* __restrict__ W1l, const float* __restrict__ W1r,
                       const float* __restrict__ x) {
    int i = blockIdx.x * blockDim.x + threadIdx.x;
    if (i < N_NODES) g_deg[i] = 0;
    if (i < N_NODES * 2) { g_p[i] = 0.f; g_q[i] = 0.f; }
    if (i < SCAN_BLKS) g_lb[i] = 0u;
    if (i < 256 * 256) {
        int k = i >> 8, n = i & 255;
        float v = (k < 128) ? W1l[k * 256 + n] : W1r[(k - 128) * 256 + n];
        g_B[n * 256 + k] = __float2half_rn(v);
    }
    if (i < N_NODES * 32) {
        int node = i >> 5, lane = i & 31;
        float4 v = *(const float4*)(x + (size_t)node * D_FEAT + lane * 4);
        uint2 pk;
        __half2 p0 = __floats2half2_rn(v.x, v.y);
        __half2 p1 = __floats2half2_rn(v.z, v.w);
        pk.x = *(uint32_t*)&p0;
        pk.y = *(uint32_t*)&p1;
        size_t off = (size_t)node * 256 + 128 + lane * 4;
        *reinterpret_cast<uint2*>(&g_A[off]) = pk;
    }
}

// hist + ordinal capture: ord[e] = position of edge e within its destination
__global__ void k_hist(const int* __restrict__ dst) {
    int e = blockIdx.x * blockDim.x + threadIdx.x;
    if (e < N_EDGES) {
        int d = dst[e];
        g_ord[e] = atomicAdd(&g_deg[d], 1);
    }
}

// ---- single-pass scan with decoupled lookback (49 blocks, one wave) ----
__global__ void k_scan() {
    __shared__ int warp_tot[32];
    __shared__ int s_base;
    int tid = threadIdx.x, lane = tid & 31, wid = tid >> 5;
    int bid = blockIdx.x;

    int idx = bid * 1024 + tid;
    int v = (idx < N_NODES) ? g_deg[idx] : 0;
    int xv = v;
#pragma unroll
    for (int o = 1; o < 32; o <<= 1) {
        int t = __shfl_up_sync(0xffffffffu, xv, o);
        if (lane >= o) xv += t;
    }
    if (lane == 31) warp_tot[wid] = xv;
    __syncthreads();
    if (wid == 0) {
        int w = warp_tot[lane];
        int xw = w;
#pragma unroll
        for (int o = 1; o < 32; o <<= 1) {
            int t = __shfl_up_sync(0xffffffffu, xw, o);
            if (lane >= o) xw += t;
        }
        warp_tot[lane] = xw;            // inclusive warp totals
        if (lane == 31) atomicExch(&g_lb[bid], (unsigned)xw | LB_FLAG);
        unsigned s0 = 0, s1 = 0;
        if (lane < bid) {
            unsigned val;
            do { val = atomicOr(&g_lb[lane], 0u); } while (!(val & LB_FLAG));
            s0 = val & ~LB_FLAG;
        }
        if (lane + 32 < bid) {
            unsigned val;
            do { val = atomicOr(&g_lb[lane + 32], 0u); } while (!(val & LB_FLAG));
            s1 = val & ~LB_FLAG;
        }
        int s = (int)(s0 + s1);
#pragma unroll
        for (int o = 16; o > 0; o >>= 1) s += __shfl_xor_sync(0xffffffffu, s, o);
        if (lane == 0) s_base = s;
    }
    __syncthreads();
    int base = s_base + ((wid > 0) ? warp_tot[wid - 1] : 0);
    int excl = base + xv - v;
    if (idx < N_NODES) {
        g_rowptr[idx] = excl;
        g_invdeg[idx] = 1.0f / (float)(v > 0 ? v : 1);
    }
    if (bid == SCAN_BLKS - 1 && tid == 1023)
        g_rowptr[N_NODES] = s_base + warp_tot[31];
}

// atomic-free scatter: nbr[rowptr[d] + ord[e]] = src[e], 2 edges/thread
__global__ void k_scatter(const int* __restrict__ src, const int* __restrict__ dst) {
    int t = blockIdx.x * blockDim.x + threadIdx.x;
    int e = t * 2;
    if (e + 1 < N_EDGES) {
        int2 d2 = *(const int2*)(dst + e);
        int2 o2 = *(const int2*)(g_ord + e);
        int2 s2 = *(const int2*)(src + e);
        g_nbr[g_rowptr[d2.x] + o2.x] = s2.x;
        g_nbr[g_rowptr[d2.y] + o2.y] = s2.y;
    } else if (e < N_EDGES) {
        g_nbr[g_rowptr[dst[e]] + g_ord[e]] = src[e];
    }
}

// agg layer1 (warp/node): mean of fp16 x, 2-edge unrolled
__global__ void k_agg1c() {
    int warp = (blockIdx.x * blockDim.x + threadIdx.x) >> 5;
    int lane = threadIdx.x & 31;
    if (warp >= N_NODES) return;
    int beg = g_rowptr[warp], end = g_rowptr[warp + 1];
    float4 acc = make_float4(0.f, 0.f, 0.f, 0.f);
    int j = beg;
    for (; j + 1 < end; j += 2) {
        int s0 = g_nbr[j], s1 = g_nbr[j + 1];
        uint2 pa = *reinterpret_cast<const uint2*>(g_A + (size_t)s0 * 256 + 128 + lane * 4);
        uint2 pb = *reinterpret_cast<const uint2*>(g_A + (size_t)s1 * 256 + 128 + lane * 4);
        float2 a0 = __half22float2(*(const __half2*)&pa.x);
        float2 a1 = __half22float2(*(const __half2*)&pa.y);
        float2 b0 = __half22float2(*(const __half2*)&pb.x);
        float2 b1 = __half22float2(*(const __half2*)&pb.y);
        acc.x += a0.x + b0.x; acc.y += a0.y + b0.y;
        acc.z += a1.x + b1.x; acc.w += a1.y + b1.y;
    }
    if (j < end) {
        int s0 = g_nbr[j];
        uint2 pa = *reinterpret_cast<const uint2*>(g_A + (size_t)s0 * 256 + 128 + lane * 4);
        float2 a0 = __half22float2(*(const __half2*)&pa.x);
        float2 a1 = __half22float2(*(const __half2*)&pa.y);
        acc.x += a0.x; acc.y += a0.y; acc.z += a1.x; acc.w += a1.y;
    }
    float id = g_invdeg[warp];
    __half2 p0 = __floats2half2_rn(acc.x * id, acc.y * id);
    __half2 p1 = __floats2half2_rn(acc.z * id, acc.w * id);
    uint2 pk;
    pk.x = *(uint32_t*)&p0;
    pk.y = *(uint32_t*)&p1;
    size_t off = (size_t)warp * 256 + lane * 4;
    *reinterpret_cast<uint2*>(&g_A[off]) = pk;
}

// ---------------- HMMA GEMM1 (fp16, ldmatrix) + fused layer-2 projections ----
__device__ __forceinline__ uint32_t smem_u32(const void* p) {
    uint32_t a;
    asm("{ .reg .u64 t; cvta.to.shared.u64 t, %1; cvt.u32.u64 %0, t; }" : "=r"(a) : "l"(p));
    return a;
}
__device__ __forceinline__ void ldm_x4(uint32_t* r, uint32_t addr) {
    asm volatile("ldmatrix.sync.aligned.m8n8.x4.shared.b16 {%0,%1,%2,%3}, [%4];"
        : "=r"(r[0]), "=r"(r[1]), "=r"(r[2]), "=r"(r[3]) : "r"(addr));
}
__device__ __forceinline__ void mma_f16(float* d, const uint32_t* a,
                                        uint32_t b0, uint32_t b1) {
    asm volatile(
        "mma.sync.aligned.m16n8k16.row.col.f32.f16.f16.f32 "
        "{%0,%1,%2,%3}, {%4,%5,%6,%7}, {%8,%9}, {%0,%1,%2,%3};"
        : "+f"(d[0]), "+f"(d[1]), "+f"(d[2]), "+f"(d[3])
        : "r"(a[0]), "r"(a[1]), "r"(a[2]), "r"(a[3]), "r"(b0), "r"(b1));
}

__global__ void __launch_bounds__(256)
k_gemm1_mma(const float* __restrict__ b1,
            const float* __restrict__ W2l, const float* __restrict__ W2r,
            float* __restrict__ h) {
    __shared__ char smA[18432];        // 128 rows x 144B
    __shared__ char smB[18432];
    __shared__ float bias[128];
    __shared__ float2 w2l[128];
    __shared__ float2 w2r[128];

    int tid  = threadIdx.x, lane = tid & 31, warp = tid >> 5;
    int warpM = warp & 3, warpN = warp >> 2;
    int m0 = blockIdx.x * 128, n0 = blockIdx.y * 128;
    uint32_t sA = smem_u32(smA), sB = smem_u32(smB);

    if (tid < 128) {
        bias[tid] = b1[n0 + tid];
        w2l[tid]  = ((const float2*)W2l)[n0 + tid];
        w2r[tid]  = ((const float2*)W2r)[n0 + tid];
    }

    float acc[2][8][4];
#pragma unroll
    for (int mt = 0; mt < 2; mt++)
#pragma unroll
        for (int nt = 0; nt < 8; nt++)
#pragma unroll
            for (int j = 0; j < 4; j++) acc[mt][nt][j] = 0.f;

#pragma unroll 1
    for (int c = 0; c < 4; c++) {
        __syncthreads();
#pragma unroll
        for (int t = 0; t < 4; t++) {
            int idx = tid + t * 256;
            int r = idx >> 3, q = idx & 7;
            size_t ga = (size_t)(m0 + r) * 256 + c * 64 + q * 8;
            size_t gb = (size_t)(n0 + r) * 256 + c * 64 + q * 8;
            uint32_t so = (uint32_t)(r * 144 + q * 16);
            *(uint4*)(smA + so) = *(const uint4*)(g_A + ga);
            *(uint4*)(smB + so) = *(const uint4*)(g_B + gb);
        }
        __syncthreads();
#pragma unroll
        for (int s = 0; s < 4; s++) {
            uint32_t a[2][4];
#pragma unroll
            for (int mt = 0; mt < 2; mt++) {
                int row = warpM * 32 + mt * 16 + (lane & 15);
                uint32_t off = (uint32_t)(row * 144 + (s * 16 + (lane >> 4) * 8) * 2);
                ldm_x4(a[mt], sA + off);
            }
            uint32_t b[4][4];
#pragma unroll
            for (int pr = 0; pr < 4; pr++) {
                int nrow = warpN * 64 + pr * 16 + ((lane >> 4) ? 8 : 0) + (lane & 7);
                int koff = s * 16 + (((lane >> 3) & 1) * 8);
                uint32_t off = (uint32_t)(nrow * 144 + koff * 2);
                ldm_x4(b[pr], sB + off);
            }
#pragma unroll
            for (int pr = 0; pr < 4; pr++) {
#pragma unroll
                for (int hf = 0; hf < 2; hf++) {
                    int nt = pr * 2 + hf;
                    uint32_t b0 = b[pr][hf * 2], b1v = b[pr][hf * 2 + 1];
#pragma unroll
                    for (int mt = 0; mt < 2; mt++)
                        mma_f16(acc[mt][nt], a[mt], b0, b1v);
                }
            }
        }
    }

    // epilogue: bias + relu + store h; fused projections p = h@W2l, q = h@W2r
#pragma unroll
    for (int mt = 0; mt < 2; mt++) {
        int rowA = m0 + warpM * 32 + mt * 16 + (lane >> 2);
        int rowB = rowA + 8;
        float pla0 = 0.f, pla1 = 0.f, pra0 = 0.f, pra1 = 0.f;
        float plb0 = 0.f, plb1 = 0.f, prb0 = 0.f, prb1 = 0.f;
#pragma unroll
        for (int nt = 0; nt < 8; nt++) {
            int cl = warpN * 64 + nt * 8 + (lane & 3) * 2;
            float bz0 = bias[cl], bz1 = bias[cl + 1];
            float h0 = fmaxf(acc[mt][nt][0] + bz0, 0.f);
            float h1 = fmaxf(acc[mt][nt][1] + bz1, 0.f);
            float h2 = fmaxf(acc[mt][nt][2] + bz0, 0.f);
            float h3 = fmaxf(acc[mt][nt][3] + bz1, 0.f);
            if (rowA < N_NODES)
                *(float2*)(h + (size_t)rowA * 256 + n0 + cl) = make_float2(h0, h1);
            if (rowB < N_NODES)
                *(float2*)(h + (size_t)rowB * 256 + n0 + cl) = make_float2(h2, h3);
            float2 wl0 = w2l[cl], wl1 = w2l[cl + 1];
            float2 wr0 = w2r[cl], wr1 = w2r[cl + 1];
            pla0 += h0 * wl0.x + h1 * wl1.x;  pla1 += h0 * wl0.y + h1 * wl1.y;
            pra0 += h0 * wr0.x + h1 * wr1.x;  pra1 += h0 * wr0.y + h1 * wr1.y;
            plb0 += h2 * wl0.x + h3 * wl1.x;  plb1 += h2 * wl0.y + h3 * wl1.y;
            prb0 += h2 * wr0.x + h3 * wr1.x;  prb1 += h2 * wr0.y + h3 * wr1.y;
        }
#pragma unroll
        for (int o = 1; o <= 2; o <<= 1) {
            pla0 += __shfl_xor_sync(0xffffffffu, pla0, o);
            pla1 += __shfl_xor_sync(0xffffffffu, pla1, o);
            pra0 += __shfl_xor_sync(0xffffffffu, pra0, o);
            pra1 += __shfl_xor_sync(0xffffffffu, pra1, o);
            plb0 += __shfl_xor_sync(0xffffffffu, plb0, o);
            plb1 += __shfl_xor_sync(0xffffffffu, plb1, o);
            prb0 += __shfl_xor_sync(0xffffffffu, prb0, o);
            prb1 += __shfl_xor_sync(0xffffffffu, prb1, o);
        }
        if ((lane & 3) == 0) {
            if (rowA < N_NODES) {
                atomicAdd(&g_p[rowA * 2 + 0], pla0);
                atomicAdd(&g_p[rowA * 2 + 1], pla1);
                atomicAdd(&g_q[rowA * 2 + 0], pra0);
                atomicAdd(&g_q[rowA * 2 + 1], pra1);
            }
            if (rowB < N_NODES) {
                atomicAdd(&g_p[rowB * 2 + 0], plb0);
                atomicAdd(&g_p[rowB * 2 + 1], plb1);
                atomicAdd(&g_q[rowB * 2 + 0], prb0);
                atomicAdd(&g_q[rowB * 2 + 1], prb1);
            }
        }
    }
}

// ---------------- layer-2: aggregate p, add q, sigmoid, store ----------------
__global__ void k_aggout(const float* __restrict__ b2, float* __restrict__ out) {
    int i = blockIdx.x * blockDim.x + threadIdx.x;
    if (i >= N_NODES) return;
    int beg = g_rowptr[i], end = g_rowptr[i + 1];
    float a0 = 0.f, a1 = 0.f;
    const float2* p2 = (const float2*)g_p;
    int j = beg;
    for (; j + 1 < end; j += 2) {
        float2 v0 = p2[g_nbr[j]];
        float2 v1 = p2[g_nbr[j + 1]];
        a0 += v0.x + v1.x; a1 += v0.y + v1.y;
    }
    if (j < end) {
        float2 v = p2[g_nbr[j]];
        a0 += v.x; a1 += v.y;
    }
    float id = g_invdeg[i];
    float v0 = a0 * id + g_q[i * 2 + 0] + b2[0];
    float v1 = a1 * id + g_q[i * 2 + 1] + b2[1];
    out[i * 2 + 0] = 1.0f / (1.0f + __expf(-v0));
    out[i * 2 + 1] = 1.0f / (1.0f + __expf(-v1));
}

// ---------------- launch ------------------------------------------------------
extern "C" void kernel_launch(void* const* d_in, const int* in_sizes, int n_in,
                              void* d_out, int out_size) {
    const float* x   = (const float*)d_in[0];
    const int*   ei  = (const int*)d_in[1];
    const float* W1l = (const float*)d_in[2];
    const float* W1r = (const float*)d_in[3];
    const float* b1  = (const float*)d_in[4];
    const float* W2l = (const float*)d_in[5];
    const float* W2r = (const float*)d_in[6];
    const float* b2  = (const float*)d_in[7];

    float* out = (float*)d_out;
    float* emb = out + (size_t)N_NODES * 2;

    const int* src = ei;
    const int* dst = ei + N_EDGES;

    // prep: zero deg/p/q/lookback + convert W1 + convert x (one kernel)
    k_prep<<<(N_NODES * 32 + 255) / 256, 256>>>(W1l, W1r, x);

    // CSR build: hist captures ordinals; scan; atomic-free scatter
    k_hist<<<(N_EDGES + 255) / 256, 256>>>(dst);
    k_scan<<<SCAN_BLKS, 1024>>>();
    k_scatter<<<(N_EDGES / 2 + 255) / 256, 256>>>(src, dst);

    // layer 1 aggregation (fp16 reads) + A conversion
    k_agg1c<<<(N_NODES + 7) / 8, 256>>>();

    // layer-1 GEMM (fp16 HMMA + ldmatrix) + fused layer-2 projections
    dim3 g1(M_TILES, 2);
    k_gemm1_mma<<<g1, 256>>>(b1, W2l, W2r, emb);

    // layer-2: aggregate 2-dim projections + output
    k_aggout<<<(N_NODES + 255) / 256, 256>>>(b2, out);
}

// round 13
// speedup vs baseline: 1.0541x; 1.0522x over previous
#include <cuda_runtime.h>
#include <cuda_fp16.h>
#include <cstdint>

#define N_NODES   50000
#define N_EDGES   800000
#define D_FEAT    128
#define HIDDEN    256
#define N_PAD     50048          // 391 * 128
#define M_TILES   391
#define SCAN_BLKS 49             // 49 * 1024 = 50176 >= N_NODES
#define LB_FLAG   0x40000000u

// ---------------- scratch (static device globals) ---------------------------
__device__ int   g_deg[N_NODES];
__device__ unsigned int g_lb[SCAN_BLKS];   // lookback: aggregate | LB_FLAG
__device__ int   g_rowptr[N_NODES + 1];
__device__ float g_invdeg[N_NODES];
__device__ int   g_ord[N_EDGES];     // per-edge ordinal within destination
__device__ int   g_nbr[N_EDGES];
__device__ __half g_A[(size_t)N_PAD * 256];   // [mean|x] fp16; pad rows stay 0
__device__ __half g_B[256 * 256];             // B^T: [n][k], k-major, fp16
// per-n0-tile projection partials: [0]=p tile0, [1]=p tile1, [2]=q tile0, [3]=q tile1
__device__ float g_pq[4][N_NODES * 2];

// ---------------- prep: zero deg/lb + convert W1 + convert x -----------------
__global__ void k_prep(const float* __restrict__ W1l, const float* __restrict__ W1r,
                       const float* __restrict__ x) {
    int i = blockIdx.x * blockDim.x + threadIdx.x;
    if (i < N_NODES) g_deg[i] = 0;
    if (i < SCAN_BLKS) g_lb[i] = 0u;
    if (i < 256 * 256) {
        int k = i >> 8, n = i & 255;
        float v = (k < 128) ? W1l[k * 256 + n] : W1r[(k - 128) * 256 + n];
        g_B[n * 256 + k] = __float2half_rn(v);
    }
    if (i < N_NODES * 32) {
        int node = i >> 5, lane = i & 31;
        float4 v = *(const float4*)(x + (size_t)node * D_FEAT + lane * 4);
        uint2 pk;
        __half2 p0 = __floats2half2_rn(v.x, v.y);
        __half2 p1 = __floats2half2_rn(v.z, v.w);
        pk.x = *(uint32_t*)&p0;
        pk.y = *(uint32_t*)&p1;
        size_t off = (size_t)node * 256 + 128 + lane * 4;
        *reinterpret_cast<uint2*>(&g_A[off]) = pk;
    }
}

// hist + ordinal capture, 2 edges/thread
__global__ void k_hist(const int* __restrict__ dst) {
    int t = blockIdx.x * blockDim.x + threadIdx.x;
    int e = t * 2;
    if (e + 1 < N_EDGES) {
        int2 d2 = *(const int2*)(dst + e);
        int2 o2;
        o2.x = atomicAdd(&g_deg[d2.x], 1);
        o2.y = atomicAdd(&g_deg[d2.y], 1);
        *(int2*)(g_ord + e) = o2;
    } else if (e < N_EDGES) {
        g_ord[e] = atomicAdd(&g_deg[dst[e]], 1);
    }
}

// ---- single-pass scan with decoupled lookback (49 blocks, one wave) ----
__global__ void k_scan() {
    __shared__ int warp_tot[32];
    __shared__ int s_base;
    int tid = threadIdx.x, lane = tid & 31, wid = tid >> 5;
    int bid = blockIdx.x;

    int idx = bid * 1024 + tid;
    int v = (idx < N_NODES) ? g_deg[idx] : 0;
    int xv = v;
#pragma unroll
    for (int o = 1; o < 32; o <<= 1) {
        int t = __shfl_up_sync(0xffffffffu, xv, o);
        if (lane >= o) xv += t;
    }
    if (lane == 31) warp_tot[wid] = xv;
    __syncthreads();
    if (wid == 0) {
        int w = warp_tot[lane];
        int xw = w;
#pragma unroll
        for (int o = 1; o < 32; o <<= 1) {
            int t = __shfl_up_sync(0xffffffffu, xw, o);
            if (lane >= o) xw += t;
        }
        warp_tot[lane] = xw;            // inclusive warp totals
        if (lane == 31) atomicExch(&g_lb[bid], (unsigned)xw | LB_FLAG);
        unsigned s0 = 0, s1 = 0;
        if (lane < bid) {
            unsigned val;
            do { val = atomicOr(&g_lb[lane], 0u); } while (!(val & LB_FLAG));
            s0 = val & ~LB_FLAG;
        }
        if (lane + 32 < bid) {
            unsigned val;
            do { val = atomicOr(&g_lb[lane + 32], 0u); } while (!(val & LB_FLAG));
            s1 = val & ~LB_FLAG;
        }
        int s = (int)(s0 + s1);
#pragma unroll
        for (int o = 16; o > 0; o >>= 1) s += __shfl_xor_sync(0xffffffffu, s, o);
        if (lane == 0) s_base = s;
    }
    __syncthreads();
    int base = s_base + ((wid > 0) ? warp_tot[wid - 1] : 0);
    int excl = base + xv - v;
    if (idx < N_NODES) {
        g_rowptr[idx] = excl;
        g_invdeg[idx] = 1.0f / (float)(v > 0 ? v : 1);
    }
    if (bid == SCAN_BLKS - 1 && tid == 1023)
        g_rowptr[N_NODES] = s_base + warp_tot[31];
}

// atomic-free scatter: nbr[rowptr[d] + ord[e]] = src[e], 2 edges/thread
__global__ void k_scatter(const int* __restrict__ src, const int* __restrict__ dst) {
    int t = blockIdx.x * blockDim.x + threadIdx.x;
    int e = t * 2;
    if (e + 1 < N_EDGES) {
        int2 d2 = *(const int2*)(dst + e);
        int2 o2 = *(const int2*)(g_ord + e);
        int2 s2 = *(const int2*)(src + e);
        g_nbr[g_rowptr[d2.x] + o2.x] = s2.x;
        g_nbr[g_rowptr[d2.y] + o2.y] = s2.y;
    } else if (e < N_EDGES) {
        g_nbr[g_rowptr[dst[e]] + g_ord[e]] = src[e];
    }
}

// agg layer1 (warp/node): mean of fp16 x, 2-edge unrolled
__global__ void k_agg1c() {
    int warp = (blockIdx.x * blockDim.x + threadIdx.x) >> 5;
    int lane = threadIdx.x & 31;
    if (warp >= N_NODES) return;
    int beg = g_rowptr[warp], end = g_rowptr[warp + 1];
    float4 acc = make_float4(0.f, 0.f, 0.f, 0.f);
    int j = beg;
    for (; j + 1 < end; j += 2) {
        int s0 = g_nbr[j], s1 = g_nbr[j + 1];
        uint2 pa = *reinterpret_cast<const uint2*>(g_A + (size_t)s0 * 256 + 128 + lane * 4);
        uint2 pb = *reinterpret_cast<const uint2*>(g_A + (size_t)s1 * 256 + 128 + lane * 4);
        float2 a0 = __half22float2(*(const __half2*)&pa.x);
        float2 a1 = __half22float2(*(const __half2*)&pa.y);
        float2 b0 = __half22float2(*(const __half2*)&pb.x);
        float2 b1 = __half22float2(*(const __half2*)&pb.y);
        acc.x += a0.x + b0.x; acc.y += a0.y + b0.y;
        acc.z += a1.x + b1.x; acc.w += a1.y + b1.y;
    }
    if (j < end) {
        int s0 = g_nbr[j];
        uint2 pa = *reinterpret_cast<const uint2*>(g_A + (size_t)s0 * 256 + 128 + lane * 4);
        float2 a0 = __half22float2(*(const __half2*)&pa.x);
        float2 a1 = __half22float2(*(const __half2*)&pa.y);
        acc.x += a0.x; acc.y += a0.y; acc.z += a1.x; acc.w += a1.y;
    }
    float id = g_invdeg[warp];
    __half2 p0 = __floats2half2_rn(acc.x * id, acc.y * id);
    __half2 p1 = __floats2half2_rn(acc.z * id, acc.w * id);
    uint2 pk;
    pk.x = *(uint32_t*)&p0;
    pk.y = *(uint32_t*)&p1;
    size_t off = (size_t)warp * 256 + lane * 4;
    *reinterpret_cast<uint2*>(&g_A[off]) = pk;
}

// ---------------- HMMA GEMM1 (fp16, ldmatrix) + fused layer-2 projections ----
__device__ __forceinline__ uint32_t smem_u32(const void* p) {
    uint32_t a;
    asm("{ .reg .u64 t; cvta.to.shared.u64 t, %1; cvt.u32.u64 %0, t; }" : "=r"(a) : "l"(p));
    return a;
}
__device__ __forceinline__ void ldm_x4(uint32_t* r, uint32_t addr) {
    asm volatile("ldmatrix.sync.aligned.m8n8.x4.shared.b16 {%0,%1,%2,%3}, [%4];"
        : "=r"(r[0]), "=r"(r[1]), "=r"(r[2]), "=r"(r[3]) : "r"(addr));
}
__device__ __forceinline__ void mma_f16(float* d, const uint32_t* a,
                                        uint32_t b0, uint32_t b1) {
    asm volatile(
        "mma.sync.aligned.m16n8k16.row.col.f32.f16.f16.f32 "
        "{%0,%1,%2,%3}, {%4,%5,%6,%7}, {%8,%9}, {%0,%1,%2,%3};"
        : "+f"(d[0]), "+f"(d[1]), "+f"(d[2]), "+f"(d[3])
        : "r"(a[0]), "r"(a[1]), "r"(a[2]), "r"(a[3]), "r"(b0), "r"(b1));
}

__global__ void __launch_bounds__(256, 2)
k_gemm1_mma(const float* __restrict__ b1,
            const float* __restrict__ W2l, const float* __restrict__ W2r,
            float* __restrict__ h) {
    __shared__ char smA[18432];        // 128 rows x 144B
    __shared__ char smB[18432];
    __shared__ float bias[128];
    __shared__ float2 w2l[128];
    __shared__ float2 w2r[128];

    int tid  = threadIdx.x, lane = tid & 31, warp = tid >> 5;
    int warpM = warp & 3, warpN = warp >> 2;
    int m0 = blockIdx.x * 128, n0 = blockIdx.y * 128;
    uint32_t sA = smem_u32(smA), sB = smem_u32(smB);
    float* gp = g_pq[blockIdx.y];
    float* gq = g_pq[2 + blockIdx.y];

    if (tid < 128) {
        bias[tid] = b1[n0 + tid];
        w2l[tid]  = ((const float2*)W2l)[n0 + tid];
        w2r[tid]  = ((const float2*)W2r)[n0 + tid];
    }

    float acc[2][8][4];
#pragma unroll
    for (int mt = 0; mt < 2; mt++)
#pragma unroll
        for (int nt = 0; nt < 8; nt++)
#pragma unroll
            for (int j = 0; j < 4; j++) acc[mt][nt][j] = 0.f;

#pragma unroll 1
    for (int c = 0; c < 4; c++) {
        __syncthreads();
#pragma unroll
        for (int t = 0; t < 4; t++) {
            int idx = tid + t * 256;
            int r = idx >> 3, q = idx & 7;
            size_t ga = (size_t)(m0 + r) * 256 + c * 64 + q * 8;
            size_t gb = (size_t)(n0 + r) * 256 + c * 64 + q * 8;
            uint32_t so = (uint32_t)(r * 144 + q * 16);
            *(uint4*)(smA + so) = *(const uint4*)(g_A + ga);
            *(uint4*)(smB + so) = *(const uint4*)(g_B + gb);
        }
        __syncthreads();
#pragma unroll
        for (int s = 0; s < 4; s++) {
            uint32_t a[2][4];
#pragma unroll
            for (int mt = 0; mt < 2; mt++) {
                int row = warpM * 32 + mt * 16 + (lane & 15);
                uint32_t off = (uint32_t)(row * 144 + (s * 16 + (lane >> 4) * 8) * 2);
                ldm_x4(a[mt], sA + off);
            }
            uint32_t b[4][4];
#pragma unroll
            for (int pr = 0; pr < 4; pr++) {
                int nrow = warpN * 64 + pr * 16 + ((lane >> 4) ? 8 : 0) + (lane & 7);
                int koff = s * 16 + (((lane >> 3) & 1) * 8);
                uint32_t off = (uint32_t)(nrow * 144 + koff * 2);
                ldm_x4(b[pr], sB + off);
            }
#pragma unroll
            for (int pr = 0; pr < 4; pr++) {
#pragma unroll
                for (int hf = 0; hf < 2; hf++) {
                    int nt = pr * 2 + hf;
                    uint32_t b0 = b[pr][hf * 2], b1v = b[pr][hf * 2 + 1];
#pragma unroll
                    for (int mt = 0; mt < 2; mt++)
                        mma_f16(acc[mt][nt], a[mt], b0, b1v);
                }
            }
        }
    }

    // epilogue: bias + relu + store h; per-tile projections -> plain stores
#pragma unroll
    for (int mt = 0; mt < 2; mt++) {
        int rowA = m0 + warpM * 32 + mt * 16 + (lane >> 2);
        int rowB = rowA + 8;
        float pla0 = 0.f, pla1 = 0.f, pra0 = 0.f, pra1 = 0.f;
        float plb0 = 0.f, plb1 = 0.f, prb0 = 0.f, prb1 = 0.f;
#pragma unroll
        for (int nt = 0; nt < 8; nt++) {
            int cl = warpN * 64 + nt * 8 + (lane & 3) * 2;
            float bz0 = bias[cl], bz1 = bias[cl + 1];
            float h0 = fmaxf(acc[mt][nt][0] + bz0, 0.f);
            float h1 = fmaxf(acc[mt][nt][1] + bz1, 0.f);
            float h2 = fmaxf(acc[mt][nt][2] + bz0, 0.f);
            float h3 = fmaxf(acc[mt][nt][3] + bz1, 0.f);
            if (rowA < N_NODES)
                *(float2*)(h + (size_t)rowA * 256 + n0 + cl) = make_float2(h0, h1);
            if (rowB < N_NODES)
                *(float2*)(h + (size_t)rowB * 256 + n0 + cl) = make_float2(h2, h3);
            float2 wl0 = w2l[cl], wl1 = w2l[cl + 1];
            float2 wr0 = w2r[cl], wr1 = w2r[cl + 1];
            pla0 += h0 * wl0.x + h1 * wl1.x;  pla1 += h0 * wl0.y + h1 * wl1.y;
            pra0 += h0 * wr0.x + h1 * wr1.x;  pra1 += h0 * wr0.y + h1 * wr1.y;
            plb0 += h2 * wl0.x + h3 * wl1.x;  plb1 += h2 * wl0.y + h3 * wl1.y;
            prb0 += h2 * wr0.x + h3 * wr1.x;  prb1 += h2 * wr0.y + h3 * wr1.y;
        }
        // reduce across the 8 warpN-quad lanes (n-covering lanes of this warp pair)
#pragma unroll
        for (int o = 1; o <= 2; o <<= 1) {
            pla0 += __shfl_xor_sync(0xffffffffu, pla0, o);
            pla1 += __shfl_xor_sync(0xffffffffu, pla1, o);
            pra0 += __shfl_xor_sync(0xffffffffu, pra0, o);
            pra1 += __shfl_xor_sync(0xffffffffu, pra1, o);
            plb0 += __shfl_xor_sync(0xffffffffu, plb0, o);
            plb1 += __shfl_xor_sync(0xffffffffu, plb1, o);
            prb0 += __shfl_xor_sync(0xffffffffu, prb0, o);
            prb1 += __shfl_xor_sync(0xffffffffu, prb1, o);
        }
        // two warps (warpN=0,1) cover disjoint col halves of the SAME rows ->
        // combine via smem? No: warpN halves are summed via the second set of
        // partial buffers? They share rows, so accumulate with one atomic per
        // pair is avoided by letting warpN==0 and warpN==1 write to separate
        // halves... instead reduce across warpN pairs through shared memory.
        __shared__ float red[2][128][4];   // [warpN][row-in-tile][p0,p1,q0,q1]
        int rloc = warpM * 32 + mt * 16 + (lane >> 2);
        if ((lane & 3) == 0) {
            red[warpN][rloc][0] = pla0; red[warpN][rloc][1] = pla1;
            red[warpN][rloc][2] = pra0; red[warpN][rloc][3] = pra1;
            red[warpN][rloc + 8][0] = plb0; red[warpN][rloc + 8][1] = plb1;
            red[warpN][rloc + 8][2] = prb0; red[warpN][rloc + 8][3] = prb1;
        }
        __syncthreads();
        if (warpN == 0 && (lane & 3) == 0) {
            int r0 = rloc, r1 = rloc + 8;
            if (rowA < N_NODES) {
                gp[rowA * 2 + 0] = red[0][r0][0] + red[1][r0][0];
                gp[rowA * 2 + 1] = red[0][r0][1] + red[1][r0][1];
                gq[rowA * 2 + 0] = red[0][r0][2] + red[1][r0][2];
                gq[rowA * 2 + 1] = red[0][r0][3] + red[1][r0][3];
            }
            if (rowB < N_NODES) {
                gp[rowB * 2 + 0] = red[0][r1][0] + red[1][r1][0];
                gp[rowB * 2 + 1] = red[0][r1][1] + red[1][r1][1];
                gq[rowB * 2 + 0] = red[0][r1][2] + red[1][r1][2];
                gq[rowB * 2 + 1] = red[0][r1][3] + red[1][r1][3];
            }
        }
        __syncthreads();
    }
}

// ---------------- layer-2: aggregate p (both tiles), add q, sigmoid ----------
__global__ void k_aggout(const float* __restrict__ b2, float* __restrict__ out) {
    int i = blockIdx.x * blockDim.x + threadIdx.x;
    if (i >= N_NODES) return;
    int beg = g_rowptr[i], end = g_rowptr[i + 1];
    float a0 = 0.f, a1 = 0.f;
    const float2* p0 = (const float2*)g_pq[0];
    const float2* p1 = (const float2*)g_pq[1];
    for (int j = beg; j < end; j++) {
        int s = g_nbr[j];
        float2 v0 = p0[s];
        float2 v1 = p1[s];
        a0 += v0.x + v1.x; a1 += v0.y + v1.y;
    }
    float id = g_invdeg[i];
    float v0 = a0 * id + g_pq[2][i * 2 + 0] + g_pq[3][i * 2 + 0] + b2[0];
    float v1 = a1 * id + g_pq[2][i * 2 + 1] + g_pq[3][i * 2 + 1] + b2[1];
    out[i * 2 + 0] = 1.0f / (1.0f + __expf(-v0));
    out[i * 2 + 1] = 1.0f / (1.0f + __expf(-v1));
}

// ---------------- launch ------------------------------------------------------
extern "C" void kernel_launch(void* const* d_in, const int* in_sizes, int n_in,
                              void* d_out, int out_size) {
    const float* x   = (const float*)d_in[0];
    const int*   ei  = (const int*)d_in[1];
    const float* W1l = (const float*)d_in[2];
    const float* W1r = (const float*)d_in[3];
    const float* b1  = (const float*)d_in[4];
    const float* W2l = (const float*)d_in[5];
    const float* W2r = (const float*)d_in[6];
    const float* b2  = (const float*)d_in[7];

    float* out = (float*)d_out;
    float* emb = out + (size_t)N_NODES * 2;

    const int* src = ei;
    const int* dst = ei + N_EDGES;

    // prep: zero deg/lookback + convert W1 + convert x (one kernel)
    k_prep<<<(N_NODES * 32 + 255) / 256, 256>>>(W1l, W1r, x);

    // CSR build: hist captures ordinals; scan; atomic-free scatter
    k_hist<<<(N_EDGES / 2 + 255) / 256, 256>>>(dst);
    k_scan<<<SCAN_BLKS, 1024>>>();
    k_scatter<<<(N_EDGES / 2 + 255) / 256, 256>>>(src, dst);

    // layer 1 aggregation (fp16 reads) + A conversion
    k_agg1c<<<(N_NODES + 7) / 8, 256>>>();

    // layer-1 GEMM (fp16 HMMA + ldmatrix, 2 CTAs/SM) + fused projections
    dim3 g1(M_TILES, 2);
    k_gemm1_mma<<<g1, 256>>>(b1, W2l, W2r, emb);

    // layer-2: aggregate 2-dim projections + output
    k_aggout<<<(N_NODES + 255) / 256, 256>>>(b2, out);
}

// round 14
// speedup vs baseline: 1.0720x; 1.0170x over previous
#include <cuda_runtime.h>
#include <cuda_fp16.h>
#include <cstdint>

#define N_NODES   50000
#define N_EDGES   800000
#define D_FEAT    128
#define HIDDEN    256
#define N_PAD     50048          // 391 * 128
#define M_TILES   391
#define SCAN_BLKS 49             // 49 * 1024 = 50176 >= N_NODES
#define LB_FLAG   0x40000000u

// ---------------- scratch (static device globals) ---------------------------
__device__ int   g_deg[N_NODES];
__device__ unsigned int g_lb[SCAN_BLKS];   // lookback: aggregate | LB_FLAG
__device__ int   g_rowptr[N_NODES + 1];
__device__ float g_invdeg[N_NODES];
__device__ int   g_ord[N_EDGES];     // per-edge ordinal within destination
__device__ int   g_nbr[N_EDGES];
__device__ __half g_A[(size_t)N_PAD * 256];   // [mean|x] fp16; pad rows stay 0
__device__ __half g_B[256 * 256];             // B^T: [n][k], k-major, fp16
// per-n0-tile projection partials: [0]=p tile0, [1]=p tile1, [2]=q tile0, [3]=q tile1
__device__ float g_pq[4][N_NODES * 2];
__device__ float2 g_pm[N_NODES];     // merged p (tile0+tile1)
__device__ float2 g_qm[N_NODES];     // merged q + b2

// ---------------- prep: zero deg/lb + convert W1 + convert x -----------------
__global__ void k_prep(const float* __restrict__ W1l, const float* __restrict__ W1r,
                       const float* __restrict__ x) {
    int i = blockIdx.x * blockDim.x + threadIdx.x;
    if (i < N_NODES) g_deg[i] = 0;
    if (i < SCAN_BLKS) g_lb[i] = 0u;
    if (i < 256 * 256) {
        int k = i >> 8, n = i & 255;
        float v = (k < 128) ? W1l[k * 256 + n] : W1r[(k - 128) * 256 + n];
        g_B[n * 256 + k] = __float2half_rn(v);
    }
    if (i < N_NODES * 32) {
        int node = i >> 5, lane = i & 31;
        float4 v = *(const float4*)(x + (size_t)node * D_FEAT + lane * 4);
        uint2 pk;
        __half2 p0 = __floats2half2_rn(v.x, v.y);
        __half2 p1 = __floats2half2_rn(v.z, v.w);
        pk.x = *(uint32_t*)&p0;
        pk.y = *(uint32_t*)&p1;
        size_t off = (size_t)node * 256 + 128 + lane * 4;
        *reinterpret_cast<uint2*>(&g_A[off]) = pk;
    }
}

// hist + ordinal capture, 4 edges/thread (800000 % 4 == 0)
__global__ void k_hist(const int* __restrict__ dst) {
    int t = blockIdx.x * blockDim.x + threadIdx.x;
    int e = t * 4;
    if (e + 3 < N_EDGES) {
        int4 d4 = *(const int4*)(dst + e);
        int4 o4;
        o4.x = atomicAdd(&g_deg[d4.x], 1);
        o4.y = atomicAdd(&g_deg[d4.y], 1);
        o4.z = atomicAdd(&g_deg[d4.z], 1);
        o4.w = atomicAdd(&g_deg[d4.w], 1);
        *(int4*)(g_ord + e) = o4;
    } else {
        for (; e < N_EDGES; e++) g_ord[e] = atomicAdd(&g_deg[dst[e]], 1);
    }
}

// ---- single-pass scan with decoupled lookback (49 blocks, one wave) ----
__global__ void k_scan() {
    __shared__ int warp_tot[32];
    __shared__ int s_base;
    int tid = threadIdx.x, lane = tid & 31, wid = tid >> 5;
    int bid = blockIdx.x;

    int idx = bid * 1024 + tid;
    int v = (idx < N_NODES) ? g_deg[idx] : 0;
    int xv = v;
#pragma unroll
    for (int o = 1; o < 32; o <<= 1) {
        int t = __shfl_up_sync(0xffffffffu, xv, o);
        if (lane >= o) xv += t;
    }
    if (lane == 31) warp_tot[wid] = xv;
    __syncthreads();
    if (wid == 0) {
        int w = warp_tot[lane];
        int xw = w;
#pragma unroll
        for (int o = 1; o < 32; o <<= 1) {
            int t = __shfl_up_sync(0xffffffffu, xw, o);
            if (lane >= o) xw += t;
        }
        warp_tot[lane] = xw;            // inclusive warp totals
        if (lane == 31) atomicExch(&g_lb[bid], (unsigned)xw | LB_FLAG);
        unsigned s0 = 0, s1 = 0;
        if (lane < bid) {
            unsigned val;
            do { val = atomicOr(&g_lb[lane], 0u); } while (!(val & LB_FLAG));
            s0 = val & ~LB_FLAG;
        }
        if (lane + 32 < bid) {
            unsigned val;
            do { val = atomicOr(&g_lb[lane + 32], 0u); } while (!(val & LB_FLAG));
            s1 = val & ~LB_FLAG;
        }
        int s = (int)(s0 + s1);
#pragma unroll
        for (int o = 16; o > 0; o >>= 1) s += __shfl_xor_sync(0xffffffffu, s, o);
        if (lane == 0) s_base = s;
    }
    __syncthreads();
    int base = s_base + ((wid > 0) ? warp_tot[wid - 1] : 0);
    int excl = base + xv - v;
    if (idx < N_NODES) {
        g_rowptr[idx] = excl;
        g_invdeg[idx] = 1.0f / (float)(v > 0 ? v : 1);
    }
    if (bid == SCAN_BLKS - 1 && tid == 1023)
        g_rowptr[N_NODES] = s_base + warp_tot[31];
}

// atomic-free scatter, 4 edges/thread
__global__ void k_scatter(const int* __restrict__ src, const int* __restrict__ dst) {
    int t = blockIdx.x * blockDim.x + threadIdx.x;
    int e = t * 4;
    if (e + 3 < N_EDGES) {
        int4 d4 = *(const int4*)(dst + e);
        int4 o4 = *(const int4*)(g_ord + e);
        int4 s4 = *(const int4*)(src + e);
        g_nbr[g_rowptr[d4.x] + o4.x] = s4.x;
        g_nbr[g_rowptr[d4.y] + o4.y] = s4.y;
        g_nbr[g_rowptr[d4.z] + o4.z] = s4.z;
        g_nbr[g_rowptr[d4.w] + o4.w] = s4.w;
    } else {
        for (; e < N_EDGES; e++) g_nbr[g_rowptr[dst[e]] + g_ord[e]] = src[e];
    }
}

// agg layer1 (warp/node): mean of fp16 x, 2-edge unrolled
__global__ void k_agg1c() {
    int warp = (blockIdx.x * blockDim.x + threadIdx.x) >> 5;
    int lane = threadIdx.x & 31;
    if (warp >= N_NODES) return;
    int beg = g_rowptr[warp], end = g_rowptr[warp + 1];
    float4 acc = make_float4(0.f, 0.f, 0.f, 0.f);
    int j = beg;
    for (; j + 1 < end; j += 2) {
        int s0 = g_nbr[j], s1 = g_nbr[j + 1];
        uint2 pa = *reinterpret_cast<const uint2*>(g_A + (size_t)s0 * 256 + 128 + lane * 4);
        uint2 pb = *reinterpret_cast<const uint2*>(g_A + (size_t)s1 * 256 + 128 + lane * 4);
        float2 a0 = __half22float2(*(const __half2*)&pa.x);
        float2 a1 = __half22float2(*(const __half2*)&pa.y);
        float2 b0 = __half22float2(*(const __half2*)&pb.x);
        float2 b1 = __half22float2(*(const __half2*)&pb.y);
        acc.x += a0.x + b0.x; acc.y += a0.y + b0.y;
        acc.z += a1.x + b1.x; acc.w += a1.y + b1.y;
    }
    if (j < end) {
        int s0 = g_nbr[j];
        uint2 pa = *reinterpret_cast<const uint2*>(g_A + (size_t)s0 * 256 + 128 + lane * 4);
        float2 a0 = __half22float2(*(const __half2*)&pa.x);
        float2 a1 = __half22float2(*(const __half2*)&pa.y);
        acc.x += a0.x; acc.y += a0.y; acc.z += a1.x; acc.w += a1.y;
    }
    float id = g_invdeg[warp];
    __half2 p0 = __floats2half2_rn(acc.x * id, acc.y * id);
    __half2 p1 = __floats2half2_rn(acc.z * id, acc.w * id);
    uint2 pk;
    pk.x = *(uint32_t*)&p0;
    pk.y = *(uint32_t*)&p1;
    size_t off = (size_t)warp * 256 + lane * 4;
    *reinterpret_cast<uint2*>(&g_A[off]) = pk;
}

// ---------------- HMMA GEMM1 (fp16, ldmatrix) + fused layer-2 projections ----
__device__ __forceinline__ uint32_t smem_u32(const void* p) {
    uint32_t a;
    asm("{ .reg .u64 t; cvta.to.shared.u64 t, %1; cvt.u32.u64 %0, t; }" : "=r"(a) : "l"(p));
    return a;
}
__device__ __forceinline__ void ldm_x4(uint32_t* r, uint32_t addr) {
    asm volatile("ldmatrix.sync.aligned.m8n8.x4.shared.b16 {%0,%1,%2,%3}, [%4];"
        : "=r"(r[0]), "=r"(r[1]), "=r"(r[2]), "=r"(r[3]) : "r"(addr));
}
__device__ __forceinline__ void mma_f16(float* d, const uint32_t* a,
                                        uint32_t b0, uint32_t b1) {
    asm volatile(
        "mma.sync.aligned.m16n8k16.row.col.f32.f16.f16.f32 "
        "{%0,%1,%2,%3}, {%4,%5,%6,%7}, {%8,%9}, {%0,%1,%2,%3};"
        : "+f"(d[0]), "+f"(d[1]), "+f"(d[2]), "+f"(d[3])
        : "r"(a[0]), "r"(a[1]), "r"(a[2]), "r"(a[3]), "r"(b0), "r"(b1));
}

__global__ void __launch_bounds__(256, 2)
k_gemm1_mma(const float* __restrict__ b1,
            const float* __restrict__ W2l, const float* __restrict__ W2r,
            float* __restrict__ h) {
    __shared__ char smA[18432];        // 128 rows x 144B
    __shared__ char smB[18432];
    __shared__ float bias[128];
    __shared__ float2 w2l[128];
    __shared__ float2 w2r[128];

    int tid  = threadIdx.x, lane = tid & 31, warp = tid >> 5;
    int warpM = warp & 3, warpN = warp >> 2;
    int m0 = blockIdx.x * 128, n0 = blockIdx.y * 128;
    uint32_t sA = smem_u32(smA), sB = smem_u32(smB);
    float* gp = g_pq[blockIdx.y];
    float* gq = g_pq[2 + blockIdx.y];

    if (tid < 128) {
        bias[tid] = b1[n0 + tid];
        w2l[tid]  = ((const float2*)W2l)[n0 + tid];
        w2r[tid]  = ((const float2*)W2r)[n0 + tid];
    }

    float acc[2][8][4];
#pragma unroll
    for (int mt = 0; mt < 2; mt++)
#pragma unroll
        for (int nt = 0; nt < 8; nt++)
#pragma unroll
            for (int j = 0; j < 4; j++) acc[mt][nt][j] = 0.f;

#pragma unroll 1
    for (int c = 0; c < 4; c++) {
        __syncthreads();
#pragma unroll
        for (int t = 0; t < 4; t++) {
            int idx = tid + t * 256;
            int r = idx >> 3, q = idx & 7;
            size_t ga = (size_t)(m0 + r) * 256 + c * 64 + q * 8;
            size_t gb = (size_t)(n0 + r) * 256 + c * 64 + q * 8;
            uint32_t so = (uint32_t)(r * 144 + q * 16);
            *(uint4*)(smA + so) = *(const uint4*)(g_A + ga);
            *(uint4*)(smB + so) = *(const uint4*)(g_B + gb);
        }
        __syncthreads();
#pragma unroll
        for (int s = 0; s < 4; s++) {
            uint32_t a[2][4];
#pragma unroll
            for (int mt = 0; mt < 2; mt++) {
                int row = warpM * 32 + mt * 16 + (lane & 15);
                uint32_t off = (uint32_t)(row * 144 + (s * 16 + (lane >> 4) * 8) * 2);
                ldm_x4(a[mt], sA + off);
            }
            uint32_t b[4][4];
#pragma unroll
            for (int pr = 0; pr < 4; pr++) {
                int nrow = warpN * 64 + pr * 16 + ((lane >> 4) ? 8 : 0) + (lane & 7);
                int koff = s * 16 + (((lane >> 3) & 1) * 8);
                uint32_t off = (uint32_t)(nrow * 144 + koff * 2);
                ldm_x4(b[pr], sB + off);
            }
#pragma unroll
            for (int pr = 0; pr < 4; pr++) {
#pragma unroll
                for (int hf = 0; hf < 2; hf++) {
                    int nt = pr * 2 + hf;
                    uint32_t b0 = b[pr][hf * 2], b1v = b[pr][hf * 2 + 1];
#pragma unroll
                    for (int mt = 0; mt < 2; mt++)
                        mma_f16(acc[mt][nt], a[mt], b0, b1v);
                }
            }
        }
    }

    // epilogue: bias + relu + store h; per-tile projections -> plain stores
#pragma unroll
    for (int mt = 0; mt < 2; mt++) {
        int rowA = m0 + warpM * 32 + mt * 16 + (lane >> 2);
        int rowB = rowA + 8;
        float pla0 = 0.f, pla1 = 0.f, pra0 = 0.f, pra1 = 0.f;
        float plb0 = 0.f, plb1 = 0.f, prb0 = 0.f, prb1 = 0.f;
#pragma unroll
        for (int nt = 0; nt < 8; nt++) {
            int cl = warpN * 64 + nt * 8 + (lane & 3) * 2;
            float bz0 = bias[cl], bz1 = bias[cl + 1];
            float h0 = fmaxf(acc[mt][nt][0] + bz0, 0.f);
            float h1 = fmaxf(acc[mt][nt][1] + bz1, 0.f);
            float h2 = fmaxf(acc[mt][nt][2] + bz0, 0.f);
            float h3 = fmaxf(acc[mt][nt][3] + bz1, 0.f);
            if (rowA < N_NODES)
                *(float2*)(h + (size_t)rowA * 256 + n0 + cl) = make_float2(h0, h1);
            if (rowB < N_NODES)
                *(float2*)(h + (size_t)rowB * 256 + n0 + cl) = make_float2(h2, h3);
            float2 wl0 = w2l[cl], wl1 = w2l[cl + 1];
            float2 wr0 = w2r[cl], wr1 = w2r[cl + 1];
            pla0 += h0 * wl0.x + h1 * wl1.x;  pla1 += h0 * wl0.y + h1 * wl1.y;
            pra0 += h0 * wr0.x + h1 * wr1.x;  pra1 += h0 * wr0.y + h1 * wr1.y;
            plb0 += h2 * wl0.x + h3 * wl1.x;  plb1 += h2 * wl0.y + h3 * wl1.y;
            prb0 += h2 * wr0.x + h3 * wr1.x;  prb1 += h2 * wr0.y + h3 * wr1.y;
        }
#pragma unroll
        for (int o = 1; o <= 2; o <<= 1) {
            pla0 += __shfl_xor_sync(0xffffffffu, pla0, o);
            pla1 += __shfl_xor_sync(0xffffffffu, pla1, o);
            pra0 += __shfl_xor_sync(0xffffffffu, pra0, o);
            pra1 += __shfl_xor_sync(0xffffffffu, pra1, o);
            plb0 += __shfl_xor_sync(0xffffffffu, plb0, o);
            plb1 += __shfl_xor_sync(0xffffffffu, plb1, o);
            prb0 += __shfl_xor_sync(0xffffffffu, prb0, o);
            prb1 += __shfl_xor_sync(0xffffffffu, prb1, o);
        }
        __shared__ float red[2][128][4];   // [warpN][row-in-tile][p0,p1,q0,q1]
        int rloc = warpM * 32 + mt * 16 + (lane >> 2);
        if ((lane & 3) == 0) {
            red[warpN][rloc][0] = pla0; red[warpN][rloc][1] = pla1;
            red[warpN][rloc][2] = pra0; red[warpN][rloc][3] = pra1;
            red[warpN][rloc + 8][0] = plb0; red[warpN][rloc + 8][1] = plb1;
            red[warpN][rloc + 8][2] = prb0; red[warpN][rloc + 8][3] = prb1;
        }
        __syncthreads();
        if (warpN == 0 && (lane & 3) == 0) {
            int r0 = rloc, r1 = rloc + 8;
            if (rowA < N_NODES) {
                gp[rowA * 2 + 0] = red[0][r0][0] + red[1][r0][0];
                gp[rowA * 2 + 1] = red[0][r0][1] + red[1][r0][1];
                gq[rowA * 2 + 0] = red[0][r0][2] + red[1][r0][2];
                gq[rowA * 2 + 1] = red[0][r0][3] + red[1][r0][3];
            }
            if (rowB < N_NODES) {
                gp[rowB * 2 + 0] = red[0][r1][0] + red[1][r1][0];
                gp[rowB * 2 + 1] = red[0][r1][1] + red[1][r1][1];
                gq[rowB * 2 + 0] = red[0][r1][2] + red[1][r1][2];
                gq[rowB * 2 + 1] = red[0][r1][3] + red[1][r1][3];
            }
        }
        __syncthreads();
    }
}

// ---------------- merge p/q tiles (single coalesced pass) --------------------
__global__ void k_merge(const float* __restrict__ b2) {
    int i = blockIdx.x * blockDim.x + threadIdx.x;
    if (i >= N_NODES) return;
    g_pm[i] = make_float2(g_pq[0][i * 2 + 0] + g_pq[1][i * 2 + 0],
                          g_pq[0][i * 2 + 1] + g_pq[1][i * 2 + 1]);
    g_qm[i] = make_float2(g_pq[2][i * 2 + 0] + g_pq[3][i * 2 + 0] + b2[0],
                          g_pq[2][i * 2 + 1] + g_pq[3][i * 2 + 1] + b2[1]);
}

// ---------------- layer-2: aggregate merged p, add q, sigmoid ----------------
__global__ void k_aggout(float* __restrict__ out) {
    int i = blockIdx.x * blockDim.x + threadIdx.x;
    if (i >= N_NODES) return;
    int beg = g_rowptr[i], end = g_rowptr[i + 1];
    float a0 = 0.f, a1 = 0.f;
    int j = beg;
    for (; j + 1 < end; j += 2) {
        float2 v0 = g_pm[g_nbr[j]];
        float2 v1 = g_pm[g_nbr[j + 1]];
        a0 += v0.x + v1.x; a1 += v0.y + v1.y;
    }
    if (j < end) {
        float2 v = g_pm[g_nbr[j]];
        a0 += v.x; a1 += v.y;
    }
    float id = g_invdeg[i];
    float2 q = g_qm[i];
    float v0 = a0 * id + q.x;
    float v1 = a1 * id + q.y;
    out[i * 2 + 0] = 1.0f / (1.0f + __expf(-v0));
    out[i * 2 + 1] = 1.0f / (1.0f + __expf(-v1));
}

// ---------------- launch ------------------------------------------------------
extern "C" void kernel_launch(void* const* d_in, const int* in_sizes, int n_in,
                              void* d_out, int out_size) {
    const float* x   = (const float*)d_in[0];
    const int*   ei  = (const int*)d_in[1];
    const float* W1l = (const float*)d_in[2];
    const float* W1r = (const float*)d_in[3];
    const float* b1  = (const float*)d_in[4];
    const float* W2l = (const float*)d_in[5];
    const float* W2r = (const float*)d_in[6];
    const float* b2  = (const float*)d_in[7];

    float* out = (float*)d_out;
    float* emb = out + (size_t)N_NODES * 2;

    const int* src = ei;
    const int* dst = ei + N_EDGES;

    // prep: zero deg/lookback + convert W1 + convert x (one kernel)
    k_prep<<<(N_NODES * 32 + 255) / 256, 256>>>(W1l, W1r, x);

    // CSR build: hist captures ordinals; scan; atomic-free scatter
    k_hist<<<(N_EDGES / 4 + 255) / 256, 256>>>(dst);
    k_scan<<<SCAN_BLKS, 1024>>>();
    k_scatter<<<(N_EDGES / 4 + 255) / 256, 256>>>(src, dst);

    // layer 1 aggregation (fp16 reads) + A conversion
    k_agg1c<<<(N_NODES + 7) / 8, 256>>>();

    // layer-1 GEMM (fp16 HMMA + ldmatrix, 2 CTAs/SM) + fused projections
    dim3 g1(M_TILES, 2);
    k_gemm1_mma<<<g1, 256>>>(b1, W2l, W2r, emb);

    // merge projection tiles, then layer-2 aggregate + output
    k_merge<<<(N_NODES + 255) / 256, 256>>>(b2);
    k_aggout<<<(N_NODES + 255) / 256, 256>>>(out);
}

// round 15
// speedup vs baseline: 1.1133x; 1.0385x over previous
#include <cuda_runtime.h>
#include <cuda_fp16.h>
#include <cstdint>

#define N_NODES   50000
#define N_EDGES   800000
#define D_FEAT    128
#define HIDDEN    256
#define N_PAD     50048          // 391 * 128
#define M_TILES   391
#define SCAN_BLKS 49             // 49 * 1024 = 50176 >= N_NODES
#define LB_FLAG   0x40000000u

// ---------------- scratch (static device globals; zero-initialized) ----------
// INVARIANT: g_deg and g_lb are zero at the start of every kernel_launch —
// statically zeroed on load, and re-zeroed by k_aggout at the end of each call.
__device__ int   g_deg[N_NODES];
__device__ unsigned int g_lb[SCAN_BLKS];   // lookback: aggregate | LB_FLAG
__device__ int   g_rowptr[N_NODES + 1];
__device__ float g_invdeg[N_NODES];
__device__ int   g_ord[N_EDGES];     // per-edge ordinal within destination
__device__ int   g_nbr[N_EDGES];
__device__ __half g_A[(size_t)N_PAD * 256];   // [mean|x] fp16; pad rows stay 0
__device__ __half g_B[256 * 256];             // B^T: [n][k], k-major, fp16
// per-n0-tile projection partials: [0]=p tile0, [1]=p tile1, [2]=q tile0, [3]=q tile1
__device__ float g_pq[4][N_NODES * 2];
__device__ float2 g_pm[N_NODES];     // merged p (tile0+tile1)
__device__ float2 g_qm[N_NODES];     // merged q + b2

// ------- fused prep + hist: convert W1/x AND histogram+ordinals in one -------
// (independent work units; g_deg arrives zeroed per the invariant above)
__global__ void k_prephist(const float* __restrict__ W1l, const float* __restrict__ W1r,
                           const float* __restrict__ x, const int* __restrict__ dst) {
    int i = blockIdx.x * blockDim.x + threadIdx.x;
    if (i < 256 * 256) {
        int k = i >> 8, n = i & 255;
        float v = (k < 128) ? W1l[k * 256 + n] : W1r[(k - 128) * 256 + n];
        g_B[n * 256 + k] = __float2half_rn(v);
    }
    if (i < N_NODES * 32) {
        int node = i >> 5, lane = i & 31;
        float4 v = *(const float4*)(x + (size_t)node * D_FEAT + lane * 4);
        uint2 pk;
        __half2 p0 = __floats2half2_rn(v.x, v.y);
        __half2 p1 = __floats2half2_rn(v.z, v.w);
        pk.x = *(uint32_t*)&p0;
        pk.y = *(uint32_t*)&p1;
        size_t off = (size_t)node * 256 + 128 + lane * 4;
        *reinterpret_cast<uint2*>(&g_A[off]) = pk;
    }
    // hist: 4 edges per thread for the first 200000 threads
    int e = i * 4;
    if (e + 3 < N_EDGES) {
        int4 d4 = *(const int4*)(dst + e);
        int4 o4;
        o4.x = atomicAdd(&g_deg[d4.x], 1);
        o4.y = atomicAdd(&g_deg[d4.y], 1);
        o4.z = atomicAdd(&g_deg[d4.z], 1);
        o4.w = atomicAdd(&g_deg[d4.w], 1);
        *(int4*)(g_ord + e) = o4;
    } else if (e < N_EDGES) {
        for (; e < N_EDGES; e++) g_ord[e] = atomicAdd(&g_deg[dst[e]], 1);
    }
}

// ---- single-pass scan with decoupled lookback (49 blocks, one wave) ----
__global__ void k_scan() {
    __shared__ int warp_tot[32];
    __shared__ int s_base;
    int tid = threadIdx.x, lane = tid & 31, wid = tid >> 5;
    int bid = blockIdx.x;

    int idx = bid * 1024 + tid;
    int v = (idx < N_NODES) ? g_deg[idx] : 0;
    int xv = v;
#pragma unroll
    for (int o = 1; o < 32; o <<= 1) {
        int t = __shfl_up_sync(0xffffffffu, xv, o);
        if (lane >= o) xv += t;
    }
    if (lane == 31) warp_tot[wid] = xv;
    __syncthreads();
    if (wid == 0) {
        int w = warp_tot[lane];
        int xw = w;
#pragma unroll
        for (int o = 1; o < 32; o <<= 1) {
            int t = __shfl_up_sync(0xffffffffu, xw, o);
            if (lane >= o) xw += t;
        }
        warp_tot[lane] = xw;            // inclusive warp totals
        if (lane == 31) atomicExch(&g_lb[bid], (unsigned)xw | LB_FLAG);
        unsigned s0 = 0, s1 = 0;
        if (lane < bid) {
            unsigned val;
            do { val = atomicOr(&g_lb[lane], 0u); } while (!(val & LB_FLAG));
            s0 = val & ~LB_FLAG;
        }
        if (lane + 32 < bid) {
            unsigned val;
            do { val = atomicOr(&g_lb[lane + 32], 0u); } while (!(val & LB_FLAG));
            s1 = val & ~LB_FLAG;
        }
        int s = (int)(s0 + s1);
#pragma unroll
        for (int o = 16; o > 0; o >>= 1) s += __shfl_xor_sync(0xffffffffu, s, o);
        if (lane == 0) s_base = s;
    }
    __syncthreads();
    int base = s_base + ((wid > 0) ? warp_tot[wid - 1] : 0);
    int excl = base + xv - v;
    if (idx < N_NODES) {
        g_rowptr[idx] = excl;
        g_invdeg[idx] = 1.0f / (float)(v > 0 ? v : 1);
    }
    if (bid == SCAN_BLKS - 1 && tid == 1023)
        g_rowptr[N_NODES] = s_base + warp_tot[31];
}

// atomic-free scatter, 2 edges/thread (measured optimum)
__global__ void k_scatter(const int* __restrict__ src, const int* __restrict__ dst) {
    int t = blockIdx.x * blockDim.x + threadIdx.x;
    int e = t * 2;
    if (e + 1 < N_EDGES) {
        int2 d2 = *(const int2*)(dst + e);
        int2 o2 = *(const int2*)(g_ord + e);
        int2 s2 = *(const int2*)(src + e);
        g_nbr[g_rowptr[d2.x] + o2.x] = s2.x;
        g_nbr[g_rowptr[d2.y] + o2.y] = s2.y;
    } else if (e < N_EDGES) {
        g_nbr[g_rowptr[dst[e]] + g_ord[e]] = src[e];
    }
}

// agg layer1 (warp/node): mean of fp16 x, 2-edge unrolled
__global__ void k_agg1c() {
    int warp = (blockIdx.x * blockDim.x + threadIdx.x) >> 5;
    int lane = threadIdx.x & 31;
    if (warp >= N_NODES) return;
    int beg = g_rowptr[warp], end = g_rowptr[warp + 1];
    float4 acc = make_float4(0.f, 0.f, 0.f, 0.f);
    int j = beg;
    for (; j + 1 < end; j += 2) {
        int s0 = g_nbr[j], s1 = g_nbr[j + 1];
        uint2 pa = *reinterpret_cast<const uint2*>(g_A + (size_t)s0 * 256 + 128 + lane * 4);
        uint2 pb = *reinterpret_cast<const uint2*>(g_A + (size_t)s1 * 256 + 128 + lane * 4);
        float2 a0 = __half22float2(*(const __half2*)&pa.x);
        float2 a1 = __half22float2(*(const __half2*)&pa.y);
        float2 b0 = __half22float2(*(const __half2*)&pb.x);
        float2 b1 = __half22float2(*(const __half2*)&pb.y);
        acc.x += a0.x + b0.x; acc.y += a0.y + b0.y;
        acc.z += a1.x + b1.x; acc.w += a1.y + b1.y;
    }
    if (j < end) {
        int s0 = g_nbr[j];
        uint2 pa = *reinterpret_cast<const uint2*>(g_A + (size_t)s0 * 256 + 128 + lane * 4);
        float2 a0 = __half22float2(*(const __half2*)&pa.x);
        float2 a1 = __half22float2(*(const __half2*)&pa.y);
        acc.x += a0.x; acc.y += a0.y; acc.z += a1.x; acc.w += a1.y;
    }
    float id = g_invdeg[warp];
    __half2 p0 = __floats2half2_rn(acc.x * id, acc.y * id);
    __half2 p1 = __floats2half2_rn(acc.z * id, acc.w * id);
    uint2 pk;
    pk.x = *(uint32_t*)&p0;
    pk.y = *(uint32_t*)&p1;
    size_t off = (size_t)warp * 256 + lane * 4;
    *reinterpret_cast<uint2*>(&g_A[off]) = pk;
}

// ---------------- HMMA GEMM1 (fp16, ldmatrix) + fused layer-2 projections ----
__device__ __forceinline__ uint32_t smem_u32(const void* p) {
    uint32_t a;
    asm("{ .reg .u64 t; cvta.to.shared.u64 t, %1; cvt.u32.u64 %0, t; }" : "=r"(a) : "l"(p));
    return a;
}
__device__ __forceinline__ void ldm_x4(uint32_t* r, uint32_t addr) {
    asm volatile("ldmatrix.sync.aligned.m8n8.x4.shared.b16 {%0,%1,%2,%3}, [%4];"
        : "=r"(r[0]), "=r"(r[1]), "=r"(r[2]), "=r"(r[3]) : "r"(addr));
}
__device__ __forceinline__ void mma_f16(float* d, const uint32_t* a,
                                        uint32_t b0, uint32_t b1) {
    asm volatile(
        "mma.sync.aligned.m16n8k16.row.col.f32.f16.f16.f32 "
        "{%0,%1,%2,%3}, {%4,%5,%6,%7}, {%8,%9}, {%0,%1,%2,%3};"
        : "+f"(d[0]), "+f"(d[1]), "+f"(d[2]), "+f"(d[3])
        : "r"(a[0]), "r"(a[1]), "r"(a[2]), "r"(a[3]), "r"(b0), "r"(b1));
}

__global__ void __launch_bounds__(256, 2)
k_gemm1_mma(const float* __restrict__ b1,
            const float* __restrict__ W2l, const float* __restrict__ W2r,
            float* __restrict__ h) {
    __shared__ char smA[18432];        // 128 rows x 144B
    __shared__ char smB[18432];
    __shared__ float bias[128];
    __shared__ float2 w2l[128];
    __shared__ float2 w2r[128];

    int tid  = threadIdx.x, lane = tid & 31, warp = tid >> 5;
    int warpM = warp & 3, warpN = warp >> 2;
    int m0 = blockIdx.x * 128, n0 = blockIdx.y * 128;
    uint32_t sA = smem_u32(smA), sB = smem_u32(smB);
    float* gp = g_pq[blockIdx.y];
    float* gq = g_pq[2 + blockIdx.y];

    if (tid < 128) {
        bias[tid] = b1[n0 + tid];
        w2l[tid]  = ((const float2*)W2l)[n0 + tid];
        w2r[tid]  = ((const float2*)W2r)[n0 + tid];
    }

    float acc[2][8][4];
#pragma unroll
    for (int mt = 0; mt < 2; mt++)
#pragma unroll
        for (int nt = 0; nt < 8; nt++)
#pragma unroll
            for (int j = 0; j < 4; j++) acc[mt][nt][j] = 0.f;

#pragma unroll 1
    for (int c = 0; c < 4; c++) {
        __syncthreads();
#pragma unroll
        for (int t = 0; t < 4; t++) {
            int idx = tid + t * 256;
            int r = idx >> 3, q = idx & 7;
            size_t ga = (size_t)(m0 + r) * 256 + c * 64 + q * 8;
            size_t gb = (size_t)(n0 + r) * 256 + c * 64 + q * 8;
            uint32_t so = (uint32_t)(r * 144 + q * 16);
            *(uint4*)(smA + so) = *(const uint4*)(g_A + ga);
            *(uint4*)(smB + so) = *(const uint4*)(g_B + gb);
        }
        __syncthreads();
#pragma unroll
        for (int s = 0; s < 4; s++) {
            uint32_t a[2][4];
#pragma unroll
            for (int mt = 0; mt < 2; mt++) {
                int row = warpM * 32 + mt * 16 + (lane & 15);
                uint32_t off = (uint32_t)(row * 144 + (s * 16 + (lane >> 4) * 8) * 2);
                ldm_x4(a[mt], sA + off);
            }
            uint32_t b[4][4];
#pragma unroll
            for (int pr = 0; pr < 4; pr++) {
                int nrow = warpN * 64 + pr * 16 + ((lane >> 4) ? 8 : 0) + (lane & 7);
                int koff = s * 16 + (((lane >> 3) & 1) * 8);
                uint32_t off = (uint32_t)(nrow * 144 + koff * 2);
                ldm_x4(b[pr], sB + off);
            }
#pragma unroll
            for (int pr = 0; pr < 4; pr++) {
#pragma unroll
                for (int hf = 0; hf < 2; hf++) {
                    int nt = pr * 2 + hf;
                    uint32_t b0 = b[pr][hf * 2], b1v = b[pr][hf * 2 + 1];
#pragma unroll
                    for (int mt = 0; mt < 2; mt++)
                        mma_f16(acc[mt][nt], a[mt], b0, b1v);
                }
            }
        }
    }

    // epilogue: bias + relu + store h; per-tile projections -> plain stores
#pragma unroll
    for (int mt = 0; mt < 2; mt++) {
        int rowA = m0 + warpM * 32 + mt * 16 + (lane >> 2);
        int rowB = rowA + 8;
        float pla0 = 0.f, pla1 = 0.f, pra0 = 0.f, pra1 = 0.f;
        float plb0 = 0.f, plb1 = 0.f, prb0 = 0.f, prb1 = 0.f;
#pragma unroll
        for (int nt = 0; nt < 8; nt++) {
            int cl = warpN * 64 + nt * 8 + (lane & 3) * 2;
            float bz0 = bias[cl], bz1 = bias[cl + 1];
            float h0 = fmaxf(acc[mt][nt][0] + bz0, 0.f);
            float h1 = fmaxf(acc[mt][nt][1] + bz1, 0.f);
            float h2 = fmaxf(acc[mt][nt][2] + bz0, 0.f);
            float h3 = fmaxf(acc[mt][nt][3] + bz1, 0.f);
            if (rowA < N_NODES)
                *(float2*)(h + (size_t)rowA * 256 + n0 + cl) = make_float2(h0, h1);
            if (rowB < N_NODES)
                *(float2*)(h + (size_t)rowB * 256 + n0 + cl) = make_float2(h2, h3);
            float2 wl0 = w2l[cl], wl1 = w2l[cl + 1];
            float2 wr0 = w2r[cl], wr1 = w2r[cl + 1];
            pla0 += h0 * wl0.x + h1 * wl1.x;  pla1 += h0 * wl0.y + h1 * wl1.y;
            pra0 += h0 * wr0.x + h1 * wr1.x;  pra1 += h0 * wr0.y + h1 * wr1.y;
            plb0 += h2 * wl0.x + h3 * wl1.x;  plb1 += h2 * wl0.y + h3 * wl1.y;
            prb0 += h2 * wr0.x + h3 * wr1.x;  prb1 += h2 * wr0.y + h3 * wr1.y;
        }
#pragma unroll
        for (int o = 1; o <= 2; o <<= 1) {
            pla0 += __shfl_xor_sync(0xffffffffu, pla0, o);
            pla1 += __shfl_xor_sync(0xffffffffu, pla1, o);
            pra0 += __shfl_xor_sync(0xffffffffu, pra0, o);
            pra1 += __shfl_xor_sync(0xffffffffu, pra1, o);
            plb0 += __shfl_xor_sync(0xffffffffu, plb0, o);
            plb1 += __shfl_xor_sync(0xffffffffu, plb1, o);
            prb0 += __shfl_xor_sync(0xffffffffu, prb0, o);
            prb1 += __shfl_xor_sync(0xffffffffu, prb1, o);
        }
        __shared__ float red[2][128][4];   // [warpN][row-in-tile][p0,p1,q0,q1]
        int rloc = warpM * 32 + mt * 16 + (lane >> 2);
        if ((lane & 3) == 0) {
            red[warpN][rloc][0] = pla0; red[warpN][rloc][1] = pla1;
            red[warpN][rloc][2] = pra0; red[warpN][rloc][3] = pra1;
            red[warpN][rloc + 8][0] = plb0; red[warpN][rloc + 8][1] = plb1;
            red[warpN][rloc + 8][2] = prb0; red[warpN][rloc + 8][3] = prb1;
        }
        __syncthreads();
        if (warpN == 0 && (lane & 3) == 0) {
            int r0 = rloc, r1 = rloc + 8;
            if (rowA < N_NODES) {
                gp[rowA * 2 + 0] = red[0][r0][0] + red[1][r0][0];
                gp[rowA * 2 + 1] = red[0][r0][1] + red[1][r0][1];
                gq[rowA * 2 + 0] = red[0][r0][2] + red[1][r0][2];
                gq[rowA * 2 + 1] = red[0][r0][3] + red[1][r0][3];
            }
            if (rowB < N_NODES) {
                gp[rowB * 2 + 0] = red[0][r1][0] + red[1][r1][0];
                gp[rowB * 2 + 1] = red[0][r1][1] + red[1][r1][1];
                gq[rowB * 2 + 0] = red[0][r1][2] + red[1][r1][2];
                gq[rowB * 2 + 1] = red[0][r1][3] + red[1][r1][3];
            }
        }
        __syncthreads();
    }
}

// ---------------- merge p/q tiles (single coalesced pass) --------------------
__global__ void k_merge(const float* __restrict__ b2) {
    int i = blockIdx.x * blockDim.x + threadIdx.x;
    if (i >= N_NODES) return;
    g_pm[i] = make_float2(g_pq[0][i * 2 + 0] + g_pq[1][i * 2 + 0],
                          g_pq[0][i * 2 + 1] + g_pq[1][i * 2 + 1]);
    g_qm[i] = make_float2(g_pq[2][i * 2 + 0] + g_pq[3][i * 2 + 0] + b2[0],
                          g_pq[2][i * 2 + 1] + g_pq[3][i * 2 + 1] + b2[1]);
}

// ------- layer-2: aggregate merged p, add q, sigmoid + STATE CLEANUP ---------
__global__ void k_aggout(float* __restrict__ out) {
    int i = blockIdx.x * blockDim.x + threadIdx.x;
    if (i >= N_NODES) return;
    int beg = g_rowptr[i], end = g_rowptr[i + 1];
    float a0 = 0.f, a1 = 0.f;
    int j = beg;
    for (; j + 1 < end; j += 2) {
        float2 v0 = g_pm[g_nbr[j]];
        float2 v1 = g_pm[g_nbr[j + 1]];
        a0 += v0.x + v1.x; a1 += v0.y + v1.y;
    }
    if (j < end) {
        float2 v = g_pm[g_nbr[j]];
        a0 += v.x; a1 += v.y;
    }
    float id = g_invdeg[i];
    float2 q = g_qm[i];
    float v0 = a0 * id + q.x;
    float v1 = a1 * id + q.y;
    out[i * 2 + 0] = 1.0f / (1.0f + __expf(-v0));
    out[i * 2 + 1] = 1.0f / (1.0f + __expf(-v1));
    // restore the zero-state invariant for the next invocation
    g_deg[i] = 0;
    if (i < SCAN_BLKS) g_lb[i] = 0u;
}

// ---------------- launch ------------------------------------------------------
extern "C" void kernel_launch(void* const* d_in, const int* in_sizes, int n_in,
                              void* d_out, int out_size) {
    const float* x   = (const float*)d_in[0];
    const int*   ei  = (const int*)d_in[1];
    const float* W1l = (const float*)d_in[2];
    const float* W1r = (const float*)d_in[3];
    const float* b1  = (const float*)d_in[4];
    const float* W2l = (const float*)d_in[5];
    const float* W2r = (const float*)d_in[6];
    const float* b2  = (const float*)d_in[7];

    float* out = (float*)d_out;
    float* emb = out + (size_t)N_NODES * 2;

    const int* src = ei;
    const int* dst = ei + N_EDGES;

    // fused prep + hist (deg/lb arrive zeroed; conv and hist co-schedule)
    k_prephist<<<(N_NODES * 32 + 255) / 256, 256>>>(W1l, W1r, x, dst);

    // CSR: single-pass lookback scan; atomic-free scatter
    k_scan<<<SCAN_BLKS, 1024>>>();
    k_scatter<<<(N_EDGES / 2 + 255) / 256, 256>>>(src, dst);

    // layer 1 aggregation (fp16 reads) + A conversion
    k_agg1c<<<(N_NODES + 7) / 8, 256>>>();

    // layer-1 GEMM (fp16 HMMA + ldmatrix, 2 CTAs/SM) + fused projections
    dim3 g1(M_TILES, 2);
    k_gemm1_mma<<<g1, 256>>>(b1, W2l, W2r, emb);

    // merge projection tiles, then layer-2 aggregate + output + cleanup
    k_merge<<<(N_NODES + 255) / 256, 256>>>(b2);
    k_aggout<<<(N_NODES + 255) / 256, 256>>>(out);
}

// round 16
// speedup vs baseline: 1.1290x; 1.0142x over previous
#include <cuda_runtime.h>
#include <cuda_fp16.h>
#include <cstdint>

#define N_NODES   50000
#define N_EDGES   800000
#define D_FEAT    128
#define HIDDEN    256
#define N_PAD     50048          // 391 * 128
#define M_TILES   391
#define SCAN_BLKS 49             // 49 * 1024 = 50176 >= N_NODES
#define LB_FLAG   0x40000000u

// ---------------- scratch (static device globals; zero-initialized) ----------
// INVARIANT: g_deg and g_lb are zero at the start of every kernel_launch —
// statically zeroed on load, re-zeroed by k_aggout at the end of each call.
// g_pm/g_qm are zeroed by k_prephist before the GEMM accumulates into them.
__device__ int   g_deg[N_NODES];
__device__ unsigned int g_lb[SCAN_BLKS];   // lookback: aggregate | LB_FLAG
__device__ int   g_rowptr[N_NODES + 1];
__device__ float g_invdeg[N_NODES];
__device__ int   g_ord[N_EDGES];     // per-edge ordinal within destination
__device__ int   g_nbr[N_EDGES];
__device__ __half g_A[(size_t)N_PAD * 256];   // [mean|x] fp16; pad rows stay 0
__device__ __half g_B[256 * 256];             // B^T: [n][k], k-major, fp16
__device__ float g_pm[N_NODES * 2];  // merged p = h@W2l (atomic, 2 adds/loc)
__device__ float g_qm[N_NODES * 2];  // merged q = h@W2r

// ------- fused prep + hist: convert W1/x, zero pm/qm, histogram+ordinals -----
__global__ void k_prephist(const float* __restrict__ W1l, const float* __restrict__ W1r,
                           const float* __restrict__ x, const int* __restrict__ dst) {
    int i = blockIdx.x * blockDim.x + threadIdx.x;
    if (i < 256 * 256) {
        int k = i >> 8, n = i & 255;
        float v = (k < 128) ? W1l[k * 256 + n] : W1r[(k - 128) * 256 + n];
        g_B[n * 256 + k] = __float2half_rn(v);
    }
    if (i < N_NODES) {
        g_pm[i * 2] = 0.f; g_pm[i * 2 + 1] = 0.f;
        g_qm[i * 2] = 0.f; g_qm[i * 2 + 1] = 0.f;
    }
    if (i < N_NODES * 32) {
        int node = i >> 5, lane = i & 31;
        float4 v = *(const float4*)(x + (size_t)node * D_FEAT + lane * 4);
        uint2 pk;
        __half2 p0 = __floats2half2_rn(v.x, v.y);
        __half2 p1 = __floats2half2_rn(v.z, v.w);
        pk.x = *(uint32_t*)&p0;
        pk.y = *(uint32_t*)&p1;
        size_t off = (size_t)node * 256 + 128 + lane * 4;
        *reinterpret_cast<uint2*>(&g_A[off]) = pk;
    }
    // hist: 4 edges per thread (deg arrives zeroed per the invariant)
    int e = i * 4;
    if (e + 3 < N_EDGES) {
        int4 d4 = *(const int4*)(dst + e);
        int4 o4;
        o4.x = atomicAdd(&g_deg[d4.x], 1);
        o4.y = atomicAdd(&g_deg[d4.y], 1);
        o4.z = atomicAdd(&g_deg[d4.z], 1);
        o4.w = atomicAdd(&g_deg[d4.w], 1);
        *(int4*)(g_ord + e) = o4;
    } else if (e < N_EDGES) {
        for (; e < N_EDGES; e++) g_ord[e] = atomicAdd(&g_deg[dst[e]], 1);
    }
}

// ---- single-pass scan with decoupled lookback (49 blocks, one wave) ----
__global__ void k_scan() {
    __shared__ int warp_tot[32];
    __shared__ int s_base;
    int tid = threadIdx.x, lane = tid & 31, wid = tid >> 5;
    int bid = blockIdx.x;

    int idx = bid * 1024 + tid;
    int v = (idx < N_NODES) ? g_deg[idx] : 0;
    int xv = v;
#pragma unroll
    for (int o = 1; o < 32; o <<= 1) {
        int t = __shfl_up_sync(0xffffffffu, xv, o);
        if (lane >= o) xv += t;
    }
    if (lane == 31) warp_tot[wid] = xv;
    __syncthreads();
    if (wid == 0) {
        int w = warp_tot[lane];
        int xw = w;
#pragma unroll
        for (int o = 1; o < 32; o <<= 1) {
            int t = __shfl_up_sync(0xffffffffu, xw, o);
            if (lane >= o) xw += t;
        }
        warp_tot[lane] = xw;            // inclusive warp totals
        if (lane == 31) atomicExch(&g_lb[bid], (unsigned)xw | LB_FLAG);
        unsigned s0 = 0, s1 = 0;
        if (lane < bid) {
            unsigned val;
            do { val = atomicOr(&g_lb[lane], 0u); } while (!(val & LB_FLAG));
            s0 = val & ~LB_FLAG;
        }
        if (lane + 32 < bid) {
            unsigned val;
            do { val = atomicOr(&g_lb[lane + 32], 0u); } while (!(val & LB_FLAG));
            s1 = val & ~LB_FLAG;
        }
        int s = (int)(s0 + s1);
#pragma unroll
        for (int o = 16; o > 0; o >>= 1) s += __shfl_xor_sync(0xffffffffu, s, o);
        if (lane == 0) s_base = s;
    }
    __syncthreads();
    int base = s_base + ((wid > 0) ? warp_tot[wid - 1] : 0);
    int excl = base + xv - v;
    if (idx < N_NODES) {
        g_rowptr[idx] = excl;
        g_invdeg[idx] = 1.0f / (float)(v > 0 ? v : 1);
    }
    if (bid == SCAN_BLKS - 1 && tid == 1023)
        g_rowptr[N_NODES] = s_base + warp_tot[31];
}

// atomic-free scatter, 2 edges/thread
__global__ void k_scatter(const int* __restrict__ src, const int* __restrict__ dst) {
    int t = blockIdx.x * blockDim.x + threadIdx.x;
    int e = t * 2;
    if (e + 1 < N_EDGES) {
        int2 d2 = *(const int2*)(dst + e);
        int2 o2 = *(const int2*)(g_ord + e);
        int2 s2 = *(const int2*)(src + e);
        g_nbr[g_rowptr[d2.x] + o2.x] = s2.x;
        g_nbr[g_rowptr[d2.y] + o2.y] = s2.y;
    } else if (e < N_EDGES) {
        g_nbr[g_rowptr[dst[e]] + g_ord[e]] = src[e];
    }
}

// agg layer1: warp per node; half-warp per edge (2 edges/iter), uint4 loads
__global__ void k_agg1c() {
    int warp = (blockIdx.x * blockDim.x + threadIdx.x) >> 5;
    int lane = threadIdx.x & 31;
    if (warp >= N_NODES) return;
    int beg = g_rowptr[warp], end = g_rowptr[warp + 1];
    int hl = lane & 15;          // half-lane: covers feats [hl*8, hl*8+8)
    int side = lane >> 4;        // 0: even edges, 1: odd edges
    float4 a0 = make_float4(0.f, 0.f, 0.f, 0.f);
    float4 a1 = make_float4(0.f, 0.f, 0.f, 0.f);
    int j = beg;
    for (; j + 1 < end; j += 2) {
        int s = g_nbr[j + side];
        uint4 pk = *reinterpret_cast<const uint4*>(g_A + (size_t)s * 256 + 128 + hl * 8);
        float2 f0 = __half22float2(*(const __half2*)&pk.x);
        float2 f1 = __half22float2(*(const __half2*)&pk.y);
        float2 f2 = __half22float2(*(const __half2*)&pk.z);
        float2 f3 = __half22float2(*(const __half2*)&pk.w);
        a0.x += f0.x; a0.y += f0.y; a0.z += f1.x; a0.w += f1.y;
        a1.x += f2.x; a1.y += f2.y; a1.z += f3.x; a1.w += f3.y;
    }
    if (j < end && side == 0) {      // odd tail: lanes 0-15 only
        int s = g_nbr[j];
        uint4 pk = *reinterpret_cast<const uint4*>(g_A + (size_t)s * 256 + 128 + hl * 8);
        float2 f0 = __half22float2(*(const __half2*)&pk.x);
        float2 f1 = __half22float2(*(const __half2*)&pk.y);
        float2 f2 = __half22float2(*(const __half2*)&pk.z);
        float2 f3 = __half22float2(*(const __half2*)&pk.w);
        a0.x += f0.x; a0.y += f0.y; a0.z += f1.x; a0.w += f1.y;
        a1.x += f2.x; a1.y += f2.y; a1.z += f3.x; a1.w += f3.y;
    }
    // combine the two half-warp partial sums (feats match across side)
    a0.x += __shfl_xor_sync(0xffffffffu, a0.x, 16);
    a0.y += __shfl_xor_sync(0xffffffffu, a0.y, 16);
    a0.z += __shfl_xor_sync(0xffffffffu, a0.z, 16);
    a0.w += __shfl_xor_sync(0xffffffffu, a0.w, 16);
    a1.x += __shfl_xor_sync(0xffffffffu, a1.x, 16);
    a1.y += __shfl_xor_sync(0xffffffffu, a1.y, 16);
    a1.z += __shfl_xor_sync(0xffffffffu, a1.z, 16);
    a1.w += __shfl_xor_sync(0xffffffffu, a1.w, 16);
    if (side == 0) {
        float id = g_invdeg[warp];
        __half2 h0 = __floats2half2_rn(a0.x * id, a0.y * id);
        __half2 h1 = __floats2half2_rn(a0.z * id, a0.w * id);
        __half2 h2 = __floats2half2_rn(a1.x * id, a1.y * id);
        __half2 h3 = __floats2half2_rn(a1.z * id, a1.w * id);
        uint4 pk;
        pk.x = *(uint32_t*)&h0; pk.y = *(uint32_t*)&h1;
        pk.z = *(uint32_t*)&h2; pk.w = *(uint32_t*)&h3;
        *reinterpret_cast<uint4*>(g_A + (size_t)warp * 256 + hl * 8) = pk;
    }
}

// ---------------- HMMA GEMM1 (fp16, ldmatrix) + fused layer-2 projections ----
__device__ __forceinline__ uint32_t smem_u32(const void* p) {
    uint32_t a;
    asm("{ .reg .u64 t; cvta.to.shared.u64 t, %1; cvt.u32.u64 %0, t; }" : "=r"(a) : "l"(p));
    return a;
}
__device__ __forceinline__ void ldm_x4(uint32_t* r, uint32_t addr) {
    asm volatile("ldmatrix.sync.aligned.m8n8.x4.shared.b16 {%0,%1,%2,%3}, [%4];"
        : "=r"(r[0]), "=r"(r[1]), "=r"(r[2]), "=r"(r[3]) : "r"(addr));
}
__device__ __forceinline__ void mma_f16(float* d, const uint32_t* a,
                                        uint32_t b0, uint32_t b1) {
    asm volatile(
        "mma.sync.aligned.m16n8k16.row.col.f32.f16.f16.f32 "
        "{%0,%1,%2,%3}, {%4,%5,%6,%7}, {%8,%9}, {%0,%1,%2,%3};"
        : "+f"(d[0]), "+f"(d[1]), "+f"(d[2]), "+f"(d[3])
        : "r"(a[0]), "r"(a[1]), "r"(a[2]), "r"(a[3]), "r"(b0), "r"(b1));
}

__global__ void __launch_bounds__(256, 2)
k_gemm1_mma(const float* __restrict__ b1,
            const float* __restrict__ W2l, const float* __restrict__ W2r,
            float* __restrict__ h) {
    __shared__ char smA[18432];        // 128 rows x 144B
    __shared__ char smB[18432];
    __shared__ float bias[128];
    __shared__ float2 w2l[128];
    __shared__ float2 w2r[128];

    int tid  = threadIdx.x, lane = tid & 31, warp = tid >> 5;
    int warpM = warp & 3, warpN = warp >> 2;
    int m0 = blockIdx.x * 128, n0 = blockIdx.y * 128;
    uint32_t sA = smem_u32(smA), sB = smem_u32(smB);

    if (tid < 128) {
        bias[tid] = b1[n0 + tid];
        w2l[tid]  = ((const float2*)W2l)[n0 + tid];
        w2r[tid]  = ((const float2*)W2r)[n0 + tid];
    }

    float acc[2][8][4];
#pragma unroll
    for (int mt = 0; mt < 2; mt++)
#pragma unroll
        for (int nt = 0; nt < 8; nt++)
#pragma unroll
            for (int j = 0; j < 4; j++) acc[mt][nt][j] = 0.f;

#pragma unroll 1
    for (int c = 0; c < 4; c++) {
        __syncthreads();
#pragma unroll
        for (int t = 0; t < 4; t++) {
            int idx = tid + t * 256;
            int r = idx >> 3, q = idx & 7;
            size_t ga = (size_t)(m0 + r) * 256 + c * 64 + q * 8;
            size_t gb = (size_t)(n0 + r) * 256 + c * 64 + q * 8;
            uint32_t so = (uint32_t)(r * 144 + q * 16);
            *(uint4*)(smA + so) = *(const uint4*)(g_A + ga);
            *(uint4*)(smB + so) = *(const uint4*)(g_B + gb);
        }
        __syncthreads();
#pragma unroll
        for (int s = 0; s < 4; s++) {
            uint32_t a[2][4];
#pragma unroll
            for (int mt = 0; mt < 2; mt++) {
                int row = warpM * 32 + mt * 16 + (lane & 15);
                uint32_t off = (uint32_t)(row * 144 + (s * 16 + (lane >> 4) * 8) * 2);
                ldm_x4(a[mt], sA + off);
            }
            uint32_t b[4][4];
#pragma unroll
            for (int pr = 0; pr < 4; pr++) {
                int nrow = warpN * 64 + pr * 16 + ((lane >> 4) ? 8 : 0) + (lane & 7);
                int koff = s * 16 + (((lane >> 3) & 1) * 8);
                uint32_t off = (uint32_t)(nrow * 144 + koff * 2);
                ldm_x4(b[pr], sB + off);
            }
#pragma unroll
            for (int pr = 0; pr < 4; pr++) {
#pragma unroll
                for (int hf = 0; hf < 2; hf++) {
                    int nt = pr * 2 + hf;
                    uint32_t b0 = b[pr][hf * 2], b1v = b[pr][hf * 2 + 1];
#pragma unroll
                    for (int mt = 0; mt < 2; mt++)
                        mma_f16(acc[mt][nt], a[mt], b0, b1v);
                }
            }
        }
    }

    // epilogue: bias + relu + store h; projections -> atomicAdd into merged pm/qm
#pragma unroll
    for (int mt = 0; mt < 2; mt++) {
        int rowA = m0 + warpM * 32 + mt * 16 + (lane >> 2);
        int rowB = rowA + 8;
        float pla0 = 0.f, pla1 = 0.f, pra0 = 0.f, pra1 = 0.f;
        float plb0 = 0.f, plb1 = 0.f, prb0 = 0.f, prb1 = 0.f;
#pragma unroll
        for (int nt = 0; nt < 8; nt++) {
            int cl = warpN * 64 + nt * 8 + (lane & 3) * 2;
            float bz0 = bias[cl], bz1 = bias[cl + 1];
            float h0 = fmaxf(acc[mt][nt][0] + bz0, 0.f);
            float h1 = fmaxf(acc[mt][nt][1] + bz1, 0.f);
            float h2 = fmaxf(acc[mt][nt][2] + bz0, 0.f);
            float h3 = fmaxf(acc[mt][nt][3] + bz1, 0.f);
            if (rowA < N_NODES)
                *(float2*)(h + (size_t)rowA * 256 + n0 + cl) = make_float2(h0, h1);
            if (rowB < N_NODES)
                *(float2*)(h + (size_t)rowB * 256 + n0 + cl) = make_float2(h2, h3);
            float2 wl0 = w2l[cl], wl1 = w2l[cl + 1];
            float2 wr0 = w2r[cl], wr1 = w2r[cl + 1];
            pla0 += h0 * wl0.x + h1 * wl1.x;  pla1 += h0 * wl0.y + h1 * wl1.y;
            pra0 += h0 * wr0.x + h1 * wr1.x;  pra1 += h0 * wr0.y + h1 * wr1.y;
            plb0 += h2 * wl0.x + h3 * wl1.x;  plb1 += h2 * wl0.y + h3 * wl1.y;
            prb0 += h2 * wr0.x + h3 * wr1.x;  prb1 += h2 * wr0.y + h3 * wr1.y;
        }
#pragma unroll
        for (int o = 1; o <= 2; o <<= 1) {
            pla0 += __shfl_xor_sync(0xffffffffu, pla0, o);
            pla1 += __shfl_xor_sync(0xffffffffu, pla1, o);
            pra0 += __shfl_xor_sync(0xffffffffu, pra0, o);
            pra1 += __shfl_xor_sync(0xffffffffu, pra1, o);
            plb0 += __shfl_xor_sync(0xffffffffu, plb0, o);
            plb1 += __shfl_xor_sync(0xffffffffu, plb1, o);
            prb0 += __shfl_xor_sync(0xffffffffu, prb0, o);
            prb1 += __shfl_xor_sync(0xffffffffu, prb1, o);
        }
        __shared__ float red[2][128][4];   // [warpN][row-in-tile][p0,p1,q0,q1]
        int rloc = warpM * 32 + mt * 16 + (lane >> 2);
        if ((lane & 3) == 0) {
            red[warpN][rloc][0] = pla0; red[warpN][rloc][1] = pla1;
            red[warpN][rloc][2] = pra0; red[warpN][rloc][3] = pra1;
            red[warpN][rloc + 8][0] = plb0; red[warpN][rloc + 8][1] = plb1;
            red[warpN][rloc + 8][2] = prb0; red[warpN][rloc + 8][3] = prb1;
        }
        __syncthreads();
        if (warpN == 0 && (lane & 3) == 0) {
            int r0 = rloc, r1 = rloc + 8;
            if (rowA < N_NODES) {
                atomicAdd(&g_pm[rowA * 2 + 0], red[0][r0][0] + red[1][r0][0]);
                atomicAdd(&g_pm[rowA * 2 + 1], red[0][r0][1] + red[1][r0][1]);
                atomicAdd(&g_qm[rowA * 2 + 0], red[0][r0][2] + red[1][r0][2]);
                atomicAdd(&g_qm[rowA * 2 + 1], red[0][r0][3] + red[1][r0][3]);
            }
            if (rowB < N_NODES) {
                atomicAdd(&g_pm[rowB * 2 + 0], red[0][r1][0] + red[1][r1][0]);
                atomicAdd(&g_pm[rowB * 2 + 1], red[0][r1][1] + red[1][r1][1]);
                atomicAdd(&g_qm[rowB * 2 + 0], red[0][r1][2] + red[1][r1][2]);
                atomicAdd(&g_qm[rowB * 2 + 1], red[0][r1][3] + red[1][r1][3]);
            }
        }
        __syncthreads();
    }
}

// ------- layer-2: aggregate merged p, add q + b2, sigmoid + STATE CLEANUP ----
__global__ void k_aggout(const float* __restrict__ b2, float* __restrict__ out) {
    int i = blockIdx.x * blockDim.x + threadIdx.x;
    if (i >= N_NODES) return;
    int beg = g_rowptr[i], end = g_rowptr[i + 1];
    float a0 = 0.f, a1 = 0.f;
    const float2* pm = (const float2*)g_pm;
    int j = beg;
    for (; j + 1 < end; j += 2) {
        float2 v0 = pm[g_nbr[j]];
        float2 v1 = pm[g_nbr[j + 1]];
        a0 += v0.x + v1.x; a1 += v0.y + v1.y;
    }
    if (j < end) {
        float2 v = pm[g_nbr[j]];
        a0 += v.x; a1 += v.y;
    }
    float id = g_invdeg[i];
    float v0 = a0 * id + g_qm[i * 2 + 0] + b2[0];
    float v1 = a1 * id + g_qm[i * 2 + 1] + b2[1];
    out[i * 2 + 0] = 1.0f / (1.0f + __expf(-v0));
    out[i * 2 + 1] = 1.0f / (1.0f + __expf(-v1));
    // restore the zero-state invariant (g_pm/g_qm are zeroed by next prephist)
    g_deg[i] = 0;
    if (i < SCAN_BLKS) g_lb[i] = 0u;
}

// ---------------- launch ------------------------------------------------------
extern "C" void kernel_launch(void* const* d_in, const int* in_sizes, int n_in,
                              void* d_out, int out_size) {
    const float* x   = (const float*)d_in[0];
    const int*   ei  = (const int*)d_in[1];
    const float* W1l = (const float*)d_in[2];
    const float* W1r = (const float*)d_in[3];
    const float* b1  = (const float*)d_in[4];
    const float* W2l = (const float*)d_in[5];
    const float* W2r = (const float*)d_in[6];
    const float* b2  = (const float*)d_in[7];

    float* out = (float*)d_out;
    float* emb = out + (size_t)N_NODES * 2;

    const int* src = ei;
    const int* dst = ei + N_EDGES;

    // fused prep + hist + pm/qm zeroing
    k_prephist<<<(N_NODES * 32 + 255) / 256, 256>>>(W1l, W1r, x, dst);

    // CSR: single-pass lookback scan; atomic-free scatter
    k_scan<<<SCAN_BLKS, 1024>>>();
    k_scatter<<<(N_EDGES / 2 + 255) / 256, 256>>>(src, dst);

    // layer 1 aggregation (half-warp split, uint4 fp16 reads)
    k_agg1c<<<(N_NODES + 7) / 8, 256>>>();

    // layer-1 GEMM (fp16 HMMA + ldmatrix) + projections atomically merged
    dim3 g1(M_TILES, 2);
    k_gemm1_mma<<<g1, 256>>>(b1, W2l, W2r, emb);

    // layer-2 aggregate + output + cleanup
    k_aggout<<<(N_NODES + 255) / 256, 256>>>(b2, out);
}

// round 17
// speedup vs baseline: 1.1321x; 1.0027x over previous
#include <cuda_runtime.h>
#include <cuda_fp16.h>
#include <cstdint>

#define N_NODES   50000
#define N_EDGES   800000
#define D_FEAT    128
#define HIDDEN    256
#define N_PAD     50048          // 391 * 128
#define M_TILES   391
#define SCAN_BLKS 49             // 49 * 1024 = 50176 >= N_NODES
#define LB_FLAG   0x40000000u
#define SS_BLKS   391            // 391 * 2048 = 800768 >= N_EDGES

// ---------------- scratch (static device globals; zero-initialized) ----------
// INVARIANT: g_deg, g_lb, g_ctr are zero at the start of every kernel_launch —
// statically zeroed on load, re-zeroed by k_aggout at the end of each call.
// g_pm/g_qm are zeroed by k_prephist before the GEMM accumulates into them.
__device__ int   g_deg[N_NODES];
__device__ unsigned int g_lb[SCAN_BLKS];   // lookback: aggregate | LB_FLAG
__device__ unsigned int g_ctr;             // scan-done counter
__device__ int   g_rowptr[N_NODES + 1];
__device__ float g_invdeg[N_NODES];
__device__ int   g_ord[N_EDGES];     // per-edge ordinal within destination
__device__ int   g_nbr[N_EDGES];
__device__ __half g_A[(size_t)N_PAD * 256];   // [mean|x] fp16; pad rows stay 0
__device__ __half g_B[256 * 256];             // B^T: [n][k], k-major, fp16
__device__ float g_pm[N_NODES * 2];  // merged p = h@W2l (atomic, 2 adds/loc)
__device__ float g_qm[N_NODES * 2];  // merged q = h@W2r

// ------- fused prep + hist: convert W1/x, zero pm/qm, histogram+ordinals -----
__global__ void k_prephist(const float* __restrict__ W1l, const float* __restrict__ W1r,
                           const float* __restrict__ x, const int* __restrict__ dst) {
    int i = blockIdx.x * blockDim.x + threadIdx.x;
    if (i < 256 * 256) {
        int k = i >> 8, n = i & 255;
        float v = (k < 128) ? W1l[k * 256 + n] : W1r[(k - 128) * 256 + n];
        g_B[n * 256 + k] = __float2half_rn(v);
    }
    if (i < N_NODES) {
        g_pm[i * 2] = 0.f; g_pm[i * 2 + 1] = 0.f;
        g_qm[i * 2] = 0.f; g_qm[i * 2 + 1] = 0.f;
    }
    if (i < N_NODES * 32) {
        int node = i >> 5, lane = i & 31;
        float4 v = *(const float4*)(x + (size_t)node * D_FEAT + lane * 4);
        uint2 pk;
        __half2 p0 = __floats2half2_rn(v.x, v.y);
        __half2 p1 = __floats2half2_rn(v.z, v.w);
        pk.x = *(uint32_t*)&p0;
        pk.y = *(uint32_t*)&p1;
        size_t off = (size_t)node * 256 + 128 + lane * 4;
        *reinterpret_cast<uint2*>(&g_A[off]) = pk;
    }
    // hist: 4 edges per thread (deg arrives zeroed per the invariant)
    int e = i * 4;
    if (e + 3 < N_EDGES) {
        int4 d4 = *(const int4*)(dst + e);
        int4 o4;
        o4.x = atomicAdd(&g_deg[d4.x], 1);
        o4.y = atomicAdd(&g_deg[d4.y], 1);
        o4.z = atomicAdd(&g_deg[d4.z], 1);
        o4.w = atomicAdd(&g_deg[d4.w], 1);
        *(int4*)(g_ord + e) = o4;
    } else if (e < N_EDGES) {
        for (; e < N_EDGES; e++) g_ord[e] = atomicAdd(&g_deg[dst[e]], 1);
    }
}

// ---- fused scan + scatter: blocks 0-48 scan (lookback), all blocks scatter --
__global__ void __launch_bounds__(1024)
k_scanscatter(const int* __restrict__ src, const int* __restrict__ dst) {
    __shared__ int warp_tot[32];
    __shared__ int s_base;
    int tid = threadIdx.x, lane = tid & 31, wid = tid >> 5;
    int bid = blockIdx.x;

    if (bid < SCAN_BLKS) {
        int idx = bid * 1024 + tid;
        int v = (idx < N_NODES) ? g_deg[idx] : 0;
        int xv = v;
#pragma unroll
        for (int o = 1; o < 32; o <<= 1) {
            int t = __shfl_up_sync(0xffffffffu, xv, o);
            if (lane >= o) xv += t;
        }
        if (lane == 31) warp_tot[wid] = xv;
        __syncthreads();
        if (wid == 0) {
            int w = warp_tot[lane];
            int xw = w;
#pragma unroll
            for (int o = 1; o < 32; o <<= 1) {
                int t = __shfl_up_sync(0xffffffffu, xw, o);
                if (lane >= o) xw += t;
            }
            warp_tot[lane] = xw;        // inclusive warp totals
            if (lane == 31) atomicExch(&g_lb[bid], (unsigned)xw | LB_FLAG);
            unsigned s0 = 0, s1 = 0;
            if (lane < bid) {
                unsigned val;
                do { val = atomicOr(&g_lb[lane], 0u); } while (!(val & LB_FLAG));
                s0 = val & ~LB_FLAG;
            }
            if (lane + 32 < bid) {
                unsigned val;
                do { val = atomicOr(&g_lb[lane + 32], 0u); } while (!(val & LB_FLAG));
                s1 = val & ~LB_FLAG;
            }
            int s = (int)(s0 + s1);
#pragma unroll
            for (int o = 16; o > 0; o >>= 1) s += __shfl_xor_sync(0xffffffffu, s, o);
            if (lane == 0) s_base = s;
        }
        __syncthreads();
        int base = s_base + ((wid > 0) ? warp_tot[wid - 1] : 0);
        int excl = base + xv - v;
        if (idx < N_NODES) {
            g_rowptr[idx] = excl;
            g_invdeg[idx] = 1.0f / (float)(v > 0 ? v : 1);
        }
        if (bid == SCAN_BLKS - 1 && tid == 1023)
            g_rowptr[N_NODES] = s_base + warp_tot[31];
        // publish completion
        __syncthreads();
        __threadfence();
        if (tid == 0) atomicAdd(&g_ctr, 1u);
    }

    // wait for all scan blocks, then scatter this block's 2048-edge slice
    if (tid == 0) {
        unsigned c;
        do { c = atomicOr(&g_ctr, 0u); } while (c < SCAN_BLKS);
    }
    __syncthreads();

    int e = bid * 2048 + tid * 2;
    if (e + 1 < N_EDGES) {
        int2 d2 = *(const int2*)(dst + e);
        int2 o2 = *(const int2*)(g_ord + e);
        int2 s2 = *(const int2*)(src + e);
        g_nbr[g_rowptr[d2.x] + o2.x] = s2.x;
        g_nbr[g_rowptr[d2.y] + o2.y] = s2.y;
    } else if (e < N_EDGES) {
        g_nbr[g_rowptr[dst[e]] + g_ord[e]] = src[e];
    }
}

// agg layer1 (warp/node): mean of fp16 x, 2-edge unrolled (R15 measured-best)
__global__ void k_agg1c() {
    int warp = (blockIdx.x * blockDim.x + threadIdx.x) >> 5;
    int lane = threadIdx.x & 31;
    if (warp >= N_NODES) return;
    int beg = g_rowptr[warp], end = g_rowptr[warp + 1];
    float4 acc = make_float4(0.f, 0.f, 0.f, 0.f);
    int j = beg;
    for (; j + 1 < end; j += 2) {
        int s0 = g_nbr[j], s1 = g_nbr[j + 1];
        uint2 pa = *reinterpret_cast<const uint2*>(g_A + (size_t)s0 * 256 + 128 + lane * 4);
        uint2 pb = *reinterpret_cast<const uint2*>(g_A + (size_t)s1 * 256 + 128 + lane * 4);
        float2 a0 = __half22float2(*(const __half2*)&pa.x);
        float2 a1 = __half22float2(*(const __half2*)&pa.y);
        float2 b0 = __half22float2(*(const __half2*)&pb.x);
        float2 b1 = __half22float2(*(const __half2*)&pb.y);
        acc.x += a0.x + b0.x; acc.y += a0.y + b0.y;
        acc.z += a1.x + b1.x; acc.w += a1.y + b1.y;
    }
    if (j < end) {
        int s0 = g_nbr[j];
        uint2 pa = *reinterpret_cast<const uint2*>(g_A + (size_t)s0 * 256 + 128 + lane * 4);
        float2 a0 = __half22float2(*(const __half2*)&pa.x);
        float2 a1 = __half22float2(*(const __half2*)&pa.y);
        acc.x += a0.x; acc.y += a0.y; acc.z += a1.x; acc.w += a1.y;
    }
    float id = g_invdeg[warp];
    __half2 p0 = __floats2half2_rn(acc.x * id, acc.y * id);
    __half2 p1 = __floats2half2_rn(acc.z * id, acc.w * id);
    uint2 pk;
    pk.x = *(uint32_t*)&p0;
    pk.y = *(uint32_t*)&p1;
    size_t off = (size_t)warp * 256 + lane * 4;
    *reinterpret_cast<uint2*>(&g_A[off]) = pk;
}

// ---------------- HMMA GEMM1 (fp16, ldmatrix) + fused layer-2 projections ----
__device__ __forceinline__ uint32_t smem_u32(const void* p) {
    uint32_t a;
    asm("{ .reg .u64 t; cvta.to.shared.u64 t, %1; cvt.u32.u64 %0, t; }" : "=r"(a) : "l"(p));
    return a;
}
__device__ __forceinline__ void ldm_x4(uint32_t* r, uint32_t addr) {
    asm volatile("ldmatrix.sync.aligned.m8n8.x4.shared.b16 {%0,%1,%2,%3}, [%4];"
        : "=r"(r[0]), "=r"(r[1]), "=r"(r[2]), "=r"(r[3]) : "r"(addr));
}
__device__ __forceinline__ void mma_f16(float* d, const uint32_t* a,
                                        uint32_t b0, uint32_t b1) {
    asm volatile(
        "mma.sync.aligned.m16n8k16.row.col.f32.f16.f16.f32 "
        "{%0,%1,%2,%3}, {%4,%5,%6,%7}, {%8,%9}, {%0,%1,%2,%3};"
        : "+f"(d[0]), "+f"(d[1]), "+f"(d[2]), "+f"(d[3])
        : "r"(a[0]), "r"(a[1]), "r"(a[2]), "r"(a[3]), "r"(b0), "r"(b1));
}

__global__ void __launch_bounds__(256, 2)
k_gemm1_mma(const float* __restrict__ b1,
            const float* __restrict__ W2l, const float* __restrict__ W2r,
            float* __restrict__ h) {
    __shared__ char smA[18432];        // 128 rows x 144B
    __shared__ char smB[18432];
    __shared__ float bias[128];
    __shared__ float2 w2l[128];
    __shared__ float2 w2r[128];

    int tid  = threadIdx.x, lane = tid & 31, warp = tid >> 5;
    int warpM = warp & 3, warpN = warp >> 2;
    int m0 = blockIdx.x * 128, n0 = blockIdx.y * 128;
    uint32_t sA = smem_u32(smA), sB = smem_u32(smB);

    if (tid < 128) {
        bias[tid] = b1[n0 + tid];
        w2l[tid]  = ((const float2*)W2l)[n0 + tid];
        w2r[tid]  = ((const float2*)W2r)[n0 + tid];
    }

    float acc[2][8][4];
#pragma unroll
    for (int mt = 0; mt < 2; mt++)
#pragma unroll
        for (int nt = 0; nt < 8; nt++)
#pragma unroll
            for (int j = 0; j < 4; j++) acc[mt][nt][j] = 0.f;

#pragma unroll 1
    for (int c = 0; c < 4; c++) {
        __syncthreads();
#pragma unroll
        for (int t = 0; t < 4; t++) {
            int idx = tid + t * 256;
            int r = idx >> 3, q = idx & 7;
            size_t ga = (size_t)(m0 + r) * 256 + c * 64 + q * 8;
            size_t gb = (size_t)(n0 + r) * 256 + c * 64 + q * 8;
            uint32_t so = (uint32_t)(r * 144 + q * 16);
            *(uint4*)(smA + so) = *(const uint4*)(g_A + ga);
            *(uint4*)(smB + so) = *(const uint4*)(g_B + gb);
        }
        __syncthreads();
#pragma unroll
        for (int s = 0; s < 4; s++) {
            uint32_t a[2][4];
#pragma unroll
            for (int mt = 0; mt < 2; mt++) {
                int row = warpM * 32 + mt * 16 + (lane & 15);
                uint32_t off = (uint32_t)(row * 144 + (s * 16 + (lane >> 4) * 8) * 2);
                ldm_x4(a[mt], sA + off);
            }
            uint32_t b[4][4];
#pragma unroll
            for (int pr = 0; pr < 4; pr++) {
                int nrow = warpN * 64 + pr * 16 + ((lane >> 4) ? 8 : 0) + (lane & 7);
                int koff = s * 16 + (((lane >> 3) & 1) * 8);
                uint32_t off = (uint32_t)(nrow * 144 + koff * 2);
                ldm_x4(b[pr], sB + off);
            }
#pragma unroll
            for (int pr = 0; pr < 4; pr++) {
#pragma unroll
                for (int hf = 0; hf < 2; hf++) {
                    int nt = pr * 2 + hf;
                    uint32_t b0 = b[pr][hf * 2], b1v = b[pr][hf * 2 + 1];
#pragma unroll
                    for (int mt = 0; mt < 2; mt++)
                        mma_f16(acc[mt][nt], a[mt], b0, b1v);
                }
            }
        }
    }

    // epilogue: bias + relu + store h; projections -> atomicAdd into merged pm/qm
#pragma unroll
    for (int mt = 0; mt < 2; mt++) {
        int rowA = m0 + warpM * 32 + mt * 16 + (lane >> 2);
        int rowB = rowA + 8;
        float pla0 = 0.f, pla1 = 0.f, pra0 = 0.f, pra1 = 0.f;
        float plb0 = 0.f, plb1 = 0.f, prb0 = 0.f, prb1 = 0.f;
#pragma unroll
        for (int nt = 0; nt < 8; nt++) {
            int cl = warpN * 64 + nt * 8 + (lane & 3) * 2;
            float bz0 = bias[cl], bz1 = bias[cl + 1];
            float h0 = fmaxf(acc[mt][nt][0] + bz0, 0.f);
            float h1 = fmaxf(acc[mt][nt][1] + bz1, 0.f);
            float h2 = fmaxf(acc[mt][nt][2] + bz0, 0.f);
            float h3 = fmaxf(acc[mt][nt][3] + bz1, 0.f);
            if (rowA < N_NODES)
                *(float2*)(h + (size_t)rowA * 256 + n0 + cl) = make_float2(h0, h1);
            if (rowB < N_NODES)
                *(float2*)(h + (size_t)rowB * 256 + n0 + cl) = make_float2(h2, h3);
            float2 wl0 = w2l[cl], wl1 = w2l[cl + 1];
            float2 wr0 = w2r[cl], wr1 = w2r[cl + 1];
            pla0 += h0 * wl0.x + h1 * wl1.x;  pla1 += h0 * wl0.y + h1 * wl1.y;
            pra0 += h0 * wr0.x + h1 * wr1.x;  pra1 += h0 * wr0.y + h1 * wr1.y;
            plb0 += h2 * wl0.x + h3 * wl1.x;  plb1 += h2 * wl0.y + h3 * wl1.y;
            prb0 += h2 * wr0.x + h3 * wr1.x;  prb1 += h2 * wr0.y + h3 * wr1.y;
        }
#pragma unroll
        for (int o = 1; o <= 2; o <<= 1) {
            pla0 += __shfl_xor_sync(0xffffffffu, pla0, o);
            pla1 += __shfl_xor_sync(0xffffffffu, pla1, o);
            pra0 += __shfl_xor_sync(0xffffffffu, pra0, o);
            pra1 += __shfl_xor_sync(0xffffffffu, pra1, o);
            plb0 += __shfl_xor_sync(0xffffffffu, plb0, o);
            plb1 += __shfl_xor_sync(0xffffffffu, plb1, o);
            prb0 += __shfl_xor_sync(0xffffffffu, prb0, o);
            prb1 += __shfl_xor_sync(0xffffffffu, prb1, o);
        }
        __shared__ float red[2][128][4];   // [warpN][row-in-tile][p0,p1,q0,q1]
        int rloc = warpM * 32 + mt * 16 + (lane >> 2);
        if ((lane & 3) == 0) {
            red[warpN][rloc][0] = pla0; red[warpN][rloc][1] = pla1;
            red[warpN][rloc][2] = pra0; red[warpN][rloc][3] = pra1;
            red[warpN][rloc + 8][0] = plb0; red[warpN][rloc + 8][1] = plb1;
            red[warpN][rloc + 8][2] = prb0; red[warpN][rloc + 8][3] = prb1;
        }
        __syncthreads();
        if (warpN == 0 && (lane & 3) == 0) {
            int r0 = rloc, r1 = rloc + 8;
            if (rowA < N_NODES) {
                atomicAdd(&g_pm[rowA * 2 + 0], red[0][r0][0] + red[1][r0][0]);
                atomicAdd(&g_pm[rowA * 2 + 1], red[0][r0][1] + red[1][r0][1]);
                atomicAdd(&g_qm[rowA * 2 + 0], red[0][r0][2] + red[1][r0][2]);
                atomicAdd(&g_qm[rowA * 2 + 1], red[0][r0][3] + red[1][r0][3]);
            }
            if (rowB < N_NODES) {
                atomicAdd(&g_pm[rowB * 2 + 0], red[0][r1][0] + red[1][r1][0]);
                atomicAdd(&g_pm[rowB * 2 + 1], red[0][r1][1] + red[1][r1][1]);
                atomicAdd(&g_qm[rowB * 2 + 0], red[0][r1][2] + red[1][r1][2]);
                atomicAdd(&g_qm[rowB * 2 + 1], red[0][r1][3] + red[1][r1][3]);
            }
        }
        __syncthreads();
    }
}

// ------- layer-2: aggregate merged p, add q + b2, sigmoid + STATE CLEANUP ----
__global__ void k_aggout(const float* __restrict__ b2, float* __restrict__ out) {
    int i = blockIdx.x * blockDim.x + threadIdx.x;
    if (i >= N_NODES) return;
    int beg = g_rowptr[i], end = g_rowptr[i + 1];
    float a0 = 0.f, a1 = 0.f;
    const float2* pm = (const float2*)g_pm;
    int j = beg;
    for (; j + 1 < end; j += 2) {
        float2 v0 = pm[g_nbr[j]];
        float2 v1 = pm[g_nbr[j + 1]];
        a0 += v0.x + v1.x; a1 += v0.y + v1.y;
    }
    if (j < end) {
        float2 v = pm[g_nbr[j]];
        a0 += v.x; a1 += v.y;
    }
    float id = g_invdeg[i];
    float v0 = a0 * id + g_qm[i * 2 + 0] + b2[0];
    float v1 = a1 * id + g_qm[i * 2 + 1] + b2[1];
    out[i * 2 + 0] = 1.0f / (1.0f + __expf(-v0));
    out[i * 2 + 1] = 1.0f / (1.0f + __expf(-v1));
    // restore the zero-state invariant for the next invocation
    g_deg[i] = 0;
    if (i < SCAN_BLKS) g_lb[i] = 0u;
    if (i == 0) g_ctr = 0u;
}

// ---------------- launch ------------------------------------------------------
extern "C" void kernel_launch(void* const* d_in, const int* in_sizes, int n_in,
                              void* d_out, int out_size) {
    const float* x   = (const float*)d_in[0];
    const int*   ei  = (const int*)d_in[1];
    const float* W1l = (const float*)d_in[2];
    const float* W1r = (const float*)d_in[3];
    const float* b1  = (const float*)d_in[4];
    const float* W2l = (const float*)d_in[5];
    const float* W2r = (const float*)d_in[6];
    const float* b2  = (const float*)d_in[7];

    float* out = (float*)d_out;
    float* emb = out + (size_t)N_NODES * 2;

    const int* src = ei;
    const int* dst = ei + N_EDGES;

    // fused prep + hist + pm/qm zeroing
    k_prephist<<<(N_NODES * 32 + 255) / 256, 256>>>(W1l, W1r, x, dst);

    // fused CSR: scan (blocks 0-48) + scatter (all blocks)
    k_scanscatter<<<SS_BLKS, 1024>>>(src, dst);

    // layer 1 aggregation (fp16 reads, 2-edge unroll)
    k_agg1c<<<(N_NODES + 7) / 8, 256>>>();

    // layer-1 GEMM (fp16 HMMA + ldmatrix) + projections atomically merged
    dim3 g1(M_TILES, 2);
    k_gemm1_mma<<<g1, 256>>>(b1, W2l, W2r, emb);

    // layer-2 aggregate + output + cleanup
    k_aggout<<<(N_NODES + 255) / 256, 256>>>(b2, out);
}